// round 1
// baseline (speedup 1.0000x reference)
#include <cuda_runtime.h>
#include <math.h>

#define BB 8
#define HH 64
#define WW 64
#define HWSZ 4096
#define CI 128
#define CQ 16
#define CIN 512

// ---------------- scratch (static device allocations are allowed) ----------------
__device__ float g_featA[BB*CI*HWSZ];
__device__ float g_featB[BB*CI*HWSZ];
__device__ float g_q [BB*CQ*HWSZ];
__device__ float g_k [BB*CQ*HWSZ];
__device__ float g_kt[BB*CQ*HWSZ];
__device__ float g_v [BB*CI*HWSZ];
__device__ float g_vt[BB*CI*HWSZ];
__device__ float g_att[BB*HH*WW*128];

// =====================================================================
// conv3x3 (pad=1) over NCHW, optional 2nd input (virtual concat on C),
// epilogue: mode 0 = batchnorm, mode 1 = ELU(alpha=512), per 8-oc block.
// block = 256 threads, tile = 64(W) x 32(H), thread = 2x4 px, 8 oc.
// =====================================================================
__global__ void __launch_bounds__(256) conv3x3_k(
    const float* __restrict__ inA, int CinA,
    const float* __restrict__ inB, int CinB,
    const float* __restrict__ wgt,
    const float* __restrict__ bn_g, const float* __restrict__ bn_b,
    const float* __restrict__ bn_m, const float* __restrict__ bn_v,
    float* __restrict__ out, int Cout, int mode)
{
    __shared__ float s_in[4][34*72];   // 4 ic, 34 rows, pitch 72 (66 valid cols)
    __shared__ float s_w[4][9][8];     // [ic][tap][oc]

    const int t   = threadIdx.x;
    const int y0  = blockIdx.x * 32;
    const int ocg = blockIdx.y % (Cout >> 3);
    const int b   = blockIdx.y / (Cout >> 3);
    const int ocb = ocg * 8;
    const int CinT = CinA + CinB;

    const int tx = t & 15;     // px group: x = tx*4 + ix
    const int ty = t >> 4;     // py group: y = y0 + ty*2 + iy

    float acc[2][4][8];
    #pragma unroll
    for (int iy = 0; iy < 2; iy++)
        #pragma unroll
        for (int ix = 0; ix < 4; ix++)
            #pragma unroll
            for (int o = 0; o < 8; o++) acc[iy][ix][o] = 0.f;

    for (int ic0 = 0; ic0 < CinT; ic0 += 4) {
        // ---- load input tile (4 ic x 34 x 66, zero-padded borders) ----
        for (int idx = t; idx < 4*34*66; idx += 256) {
            int icl = idx / (34*66);
            int rem = idx - icl*(34*66);
            int r   = rem / 66;
            int c   = rem - r*66;
            int gy  = y0 + r - 1;
            int gx  = c - 1;
            int gic = ic0 + icl;
            float vv = 0.f;
            if (gy >= 0 && gy < 64 && gx >= 0 && gx < 64) {
                if (gic < CinA) vv = inA[((b*CinA + gic)*64 + gy)*64 + gx];
                else            vv = inB[((b*CinB + (gic - CinA))*64 + gy)*64 + gx];
            }
            s_in[icl][r*72 + c] = vv;
        }
        // ---- load weights: 8 oc x 4 ic x 9 taps ----
        for (int idx = t; idx < 288; idx += 256) {
            int o   = idx & 7;
            int kk  = (idx >> 3) % 9;
            int icl = idx / 72;
            s_w[icl][kk][o] = wgt[((ocb + o)*CinT + ic0 + icl)*9 + kk];
        }
        __syncthreads();

        #pragma unroll 1
        for (int icl = 0; icl < 4; icl++) {
            float rr[4][6];
            #pragma unroll
            for (int ry = 0; ry < 4; ry++)
                #pragma unroll
                for (int cc = 0; cc < 6; cc++)
                    rr[ry][cc] = s_in[icl][(ty*2 + ry)*72 + tx*4 + cc];

            #pragma unroll
            for (int kk = 0; kk < 9; kk++) {
                const int ky = kk / 3, kx = kk % 3;
                float4 wa = *(const float4*)&s_w[icl][kk][0];
                float4 wb = *(const float4*)&s_w[icl][kk][4];
                #pragma unroll
                for (int iy = 0; iy < 2; iy++)
                    #pragma unroll
                    for (int ix = 0; ix < 4; ix++) {
                        float xv = rr[iy + ky][ix + kx];
                        acc[iy][ix][0] += xv * wa.x;
                        acc[iy][ix][1] += xv * wa.y;
                        acc[iy][ix][2] += xv * wa.z;
                        acc[iy][ix][3] += xv * wa.w;
                        acc[iy][ix][4] += xv * wb.x;
                        acc[iy][ix][5] += xv * wb.y;
                        acc[iy][ix][6] += xv * wb.z;
                        acc[iy][ix][7] += xv * wb.w;
                    }
            }
        }
        __syncthreads();
    }

    // ---- epilogue ----
    #pragma unroll
    for (int o = 0; o < 8; o++) {
        const int oc = ocb + o;
        float sc = 1.f, bi = 0.f;
        if (mode == 0) {
            sc = bn_g[oc] / sqrtf(bn_v[oc] + 1e-5f);
            bi = bn_b[oc] - bn_m[oc] * sc;
        }
        #pragma unroll
        for (int iy = 0; iy < 2; iy++) {
            const int py = y0 + ty*2 + iy;
            float vals[4];
            #pragma unroll
            for (int ix = 0; ix < 4; ix++) {
                float a = acc[iy][ix][o];
                if (mode == 0) a = a * sc + bi;
                else if (a <= 0.f) a = 512.0f * expm1f(a);
                vals[ix] = a;
            }
            *(float4*)&out[((b*Cout + oc)*64 + py)*64 + tx*4] =
                make_float4(vals[0], vals[1], vals[2], vals[3]);
        }
    }
}

// =====================================================================
// fused q/k/v 1x1 conv: 160 oc (16 q | 16 k | 128 v), 128 ic.
// block = 256 threads, 128 px; thread = 4 px x 20 oc.
// =====================================================================
__global__ void __launch_bounds__(256) qkv_k(
    const float* __restrict__ feat,
    const float* __restrict__ wq, const float* __restrict__ bq,
    const float* __restrict__ wk, const float* __restrict__ bk,
    const float* __restrict__ wv, const float* __restrict__ bv,
    float* __restrict__ q, float* __restrict__ k, float* __restrict__ v)
{
    extern __shared__ __align__(16) float sm[];
    float* s_in = sm;               // [128 ic][128 px]
    float* s_w  = sm + 128*128;     // [128 ic][pitch 164] (160 oc)

    const int t   = threadIdx.x;
    const int pxb = blockIdx.x * 128;
    const int b   = blockIdx.y;

    const float4* f4 = (const float4*)(feat + (size_t)b*CI*HWSZ);
    for (int idx = t; idx < 128*32; idx += 256) {
        int ic = idx >> 5, p4 = idx & 31;
        ((float4*)s_in)[ic*32 + p4] = f4[ic*(HWSZ/4) + (pxb >> 2) + p4];
    }
    for (int idx = t; idx < 16*128;  idx += 256) { int oc = idx >> 7, ic = idx & 127; s_w[ic*164 + oc]       = wq[idx]; }
    for (int idx = t; idx < 16*128;  idx += 256) { int oc = idx >> 7, ic = idx & 127; s_w[ic*164 + 16 + oc]  = wk[idx]; }
    for (int idx = t; idx < 128*128; idx += 256) { int oc = idx >> 7, ic = idx & 127; s_w[ic*164 + 32 + oc]  = wv[idx]; }
    __syncthreads();

    const int l   = t & 31;          // px group: px = pxb + l*4 + i
    const int oc0 = (t >> 5) * 20;

    float acc[20][4];
    #pragma unroll
    for (int j = 0; j < 20; j++)
        #pragma unroll
        for (int i = 0; i < 4; i++) acc[j][i] = 0.f;

    for (int ic = 0; ic < 128; ic++) {
        float4 x4 = ((const float4*)s_in)[ic*32 + l];
        const float* wr = s_w + ic*164 + oc0;
        #pragma unroll
        for (int j = 0; j < 5; j++) {
            float4 w4 = *(const float4*)(wr + 4*j);
            acc[4*j+0][0] += w4.x * x4.x; acc[4*j+0][1] += w4.x * x4.y;
            acc[4*j+0][2] += w4.x * x4.z; acc[4*j+0][3] += w4.x * x4.w;
            acc[4*j+1][0] += w4.y * x4.x; acc[4*j+1][1] += w4.y * x4.y;
            acc[4*j+1][2] += w4.y * x4.z; acc[4*j+1][3] += w4.y * x4.w;
            acc[4*j+2][0] += w4.z * x4.x; acc[4*j+2][1] += w4.z * x4.y;
            acc[4*j+2][2] += w4.z * x4.z; acc[4*j+2][3] += w4.z * x4.w;
            acc[4*j+3][0] += w4.w * x4.x; acc[4*j+3][1] += w4.w * x4.y;
            acc[4*j+3][2] += w4.w * x4.z; acc[4*j+3][3] += w4.w * x4.w;
        }
    }

    #pragma unroll
    for (int j = 0; j < 20; j++) {
        const int oc = oc0 + j;
        float bias; float* dst; int o; int C;
        if (oc < 16)      { bias = bq[oc];      dst = q; o = oc;      C = CQ; }
        else if (oc < 32) { bias = bk[oc - 16]; dst = k; o = oc - 16; C = CQ; }
        else              { bias = bv[oc - 32]; dst = v; o = oc - 32; C = CI; }
        *(float4*)&dst[((size_t)b*C + o)*HWSZ + pxb + l*4] =
            make_float4(acc[j][0] + bias, acc[j][1] + bias,
                        acc[j][2] + bias, acc[j][3] + bias);
    }
}

// =====================================================================
// 64x64 spatial transpose per (b,c) plane
// =====================================================================
__global__ void __launch_bounds__(256) trans_k(const float* __restrict__ in,
                                               float* __restrict__ out)
{
    __shared__ float s[64][65];
    const float* src = in  + (size_t)blockIdx.x * 4096;
    float*       dst = out + (size_t)blockIdx.x * 4096;
    for (int idx = threadIdx.x; idx < 4096; idx += 256)
        s[idx >> 6][idx & 63] = src[idx];
    __syncthreads();
    for (int idx = threadIdx.x; idx < 4096; idx += 256)
        dst[idx] = s[idx & 63][idx >> 6];   // dst[w*64+h] = src[h*64+w]
}

// =====================================================================
// logits + softmax per (b,h): E[w][0:64]=eH (diag masked), E[w][64:128]=eW
// =====================================================================
__global__ void __launch_bounds__(256) att_k(
    const float* __restrict__ q, const float* __restrict__ k,
    const float* __restrict__ kt, float* __restrict__ att)
{
    __shared__ float qs[16*64];
    __shared__ float ks[16*64];
    __shared__ float E[64*128];

    const int t = threadIdx.x;
    const int h = blockIdx.x, b = blockIdx.y;

    for (int idx = t; idx < 1024; idx += 256) {
        int c = idx >> 6, w = idx & 63;
        qs[idx] = q[((b*CQ + c)*HH + h)*WW + w];
        ks[idx] = k[((b*CQ + c)*HH + h)*WW + w];
    }
    __syncthreads();

    for (int idx = t; idx < 2048; idx += 256) {
        const int w  = idx >> 5;
        const int j4 = idx & 31;
        float4 e = make_float4(0.f, 0.f, 0.f, 0.f);
        if (j4 < 16) {  // eH: k column at this w (via transposed k)
            for (int c = 0; c < 16; c++) {
                float qq = qs[c*64 + w];
                float4 kv = ((const float4*)kt)[((b*CQ + c)*WW + w)*16 + j4];
                e.x += qq * kv.x; e.y += qq * kv.y; e.z += qq * kv.z; e.w += qq * kv.w;
            }
            if ((h >> 2) == j4) ((float*)&e)[h & 3] = -INFINITY;  // mask g==h
        } else {        // eW: k row at this h
            for (int c = 0; c < 16; c++) {
                float qq = qs[c*64 + w];
                float4 kv = ((const float4*)ks)[c*16 + (j4 - 16)];
                e.x += qq * kv.x; e.y += qq * kv.y; e.z += qq * kv.z; e.w += qq * kv.w;
            }
        }
        ((float4*)E)[w*32 + j4] = e;
    }
    __syncthreads();

    const int lane = t & 31, wid = t >> 5;
    for (int r = 0; r < 8; r++) {
        const int w = wid*8 + r;
        float v0 = E[w*128 + lane],      v1 = E[w*128 + lane + 32];
        float v2 = E[w*128 + lane + 64], v3 = E[w*128 + lane + 96];
        float m = fmaxf(fmaxf(v0, v1), fmaxf(v2, v3));
        #pragma unroll
        for (int s = 16; s; s >>= 1) m = fmaxf(m, __shfl_xor_sync(0xffffffffu, m, s));
        float e0 = expf(v0 - m), e1 = expf(v1 - m), e2 = expf(v2 - m), e3 = expf(v3 - m);
        float sum = e0 + e1 + e2 + e3;
        #pragma unroll
        for (int s = 16; s; s >>= 1) sum += __shfl_xor_sync(0xffffffffu, sum, s);
        float inv = 1.f / sum;
        float* dst = att + (size_t)((b*HH + h)*WW + w)*128;
        dst[lane] = e0*inv; dst[lane+32] = e1*inv; dst[lane+64] = e2*inv; dst[lane+96] = e3*inv;
    }
}

// =====================================================================
// pass1: oH[b,c,h,w] = sum_g v[b,c,g,w] * aH[b,h,w,g], per (b,w) block
// writes raw oH into outb (scattered stores, coalesced reloaded in pass2)
// =====================================================================
__global__ void __launch_bounds__(256) oH_k(
    const float* __restrict__ att, const float* __restrict__ vt,
    float* __restrict__ outb)
{
    extern __shared__ __align__(16) float sm[];
    float* As = sm;           // [g][pitch 68] = aH[h,g] transposed
    float* Vs = sm + 64*68;   // [g][pitch 132] = v[c,g] transposed

    const int t = threadIdx.x;
    const int w = blockIdx.x, b = blockIdx.y;

    for (int idx = t; idx < 4096; idx += 256) {
        int hh = idx >> 6, g = idx & 63;
        As[g*68 + hh] = att[(size_t)((b*HH + hh)*WW + w)*128 + g];
    }
    for (int idx = t; idx < 8192; idx += 256) {
        int c = idx >> 6, g = idx & 63;
        Vs[g*132 + c] = vt[((b*CI + c)*WW + w)*HH + g];
    }
    __syncthreads();

    const int c0 = (t & 31) * 4;
    const int h0 = (t >> 5) * 8;
    float acc[8][4];
    #pragma unroll
    for (int i = 0; i < 8; i++)
        #pragma unroll
        for (int j = 0; j < 4; j++) acc[i][j] = 0.f;

    for (int g = 0; g < 64; g++) {
        float4 v4 = *(const float4*)&Vs[g*132 + c0];
        #pragma unroll
        for (int hi = 0; hi < 8; hi++) {
            float av = As[g*68 + h0 + hi];
            acc[hi][0] += av * v4.x; acc[hi][1] += av * v4.y;
            acc[hi][2] += av * v4.z; acc[hi][3] += av * v4.w;
        }
    }
    #pragma unroll
    for (int hi = 0; hi < 8; hi++)
        #pragma unroll
        for (int ci = 0; ci < 4; ci++)
            outb[((b*CI + c0 + ci)*HH + h0 + hi)*WW + w] = acc[hi][ci];
}

// =====================================================================
// pass2: out = feat + gamma*(oH + oW), per (b,h) block (coalesced I/O)
// =====================================================================
__global__ void __launch_bounds__(256) oW_k(
    const float* __restrict__ att, const float* __restrict__ v,
    const float* __restrict__ feat, const float* __restrict__ gamma,
    float* __restrict__ outb)
{
    extern __shared__ __align__(16) float sm[];
    float* Aw = sm;           // [w'][pitch 68] = aW[w,w'] transposed
    float* Ws = sm + 64*68;   // [w'][pitch 132] = v[c,w'] transposed

    const int t = threadIdx.x;
    const int h = blockIdx.x, b = blockIdx.y;

    for (int idx = t; idx < 4096; idx += 256) {
        int w = idx >> 6, wp = idx & 63;
        Aw[wp*68 + w] = att[(size_t)((b*HH + h)*WW + w)*128 + 64 + wp];
    }
    for (int idx = t; idx < 8192; idx += 256) {
        int c = idx >> 6, wp = idx & 63;
        Ws[wp*132 + c] = v[((b*CI + c)*HH + h)*WW + wp];
    }
    __syncthreads();

    const int c0 = (t & 31) * 4;
    const int w0 = (t >> 5) * 8;
    float acc[8][4];
    #pragma unroll
    for (int i = 0; i < 8; i++)
        #pragma unroll
        for (int j = 0; j < 4; j++) acc[i][j] = 0.f;

    for (int wp = 0; wp < 64; wp++) {
        float4 v4 = *(const float4*)&Ws[wp*132 + c0];
        #pragma unroll
        for (int wi = 0; wi < 8; wi++) {
            float av = Aw[wp*68 + w0 + wi];
            acc[wi][0] += av * v4.x; acc[wi][1] += av * v4.y;
            acc[wi][2] += av * v4.z; acc[wi][3] += av * v4.w;
        }
    }

    const float g = gamma[0];
    #pragma unroll
    for (int ci = 0; ci < 4; ci++) {
        const int base = ((b*CI + c0 + ci)*HH + h)*WW + w0;
        float4 f0 = *(const float4*)&feat[base];
        float4 f1 = *(const float4*)&feat[base + 4];
        float4 o0 = *(const float4*)&outb[base];
        float4 o1 = *(const float4*)&outb[base + 4];
        float4 r0 = make_float4(f0.x + g*(o0.x + acc[0][ci]),
                                f0.y + g*(o0.y + acc[1][ci]),
                                f0.z + g*(o0.z + acc[2][ci]),
                                f0.w + g*(o0.w + acc[3][ci]));
        float4 r1 = make_float4(f1.x + g*(o1.x + acc[4][ci]),
                                f1.y + g*(o1.y + acc[5][ci]),
                                f1.z + g*(o1.z + acc[6][ci]),
                                f1.w + g*(o1.w + acc[7][ci]));
        *(float4*)&outb[base]     = r0;
        *(float4*)&outb[base + 4] = r1;
    }
}

// =====================================================================
extern "C" void kernel_launch(void* const* d_in, const int* in_sizes, int n_in,
                              void* d_out, int out_size)
{
    (void)in_sizes; (void)n_in; (void)out_size;
    const float* x       = (const float*)d_in[0];
    const float* conva_w = (const float*)d_in[1];
    const float* bn1_g   = (const float*)d_in[2];
    const float* bn1_b   = (const float*)d_in[3];
    const float* bn1_m   = (const float*)d_in[4];
    const float* bn1_v   = (const float*)d_in[5];
    const float* wq      = (const float*)d_in[6];
    const float* bq      = (const float*)d_in[7];
    const float* wk      = (const float*)d_in[8];
    const float* bk      = (const float*)d_in[9];
    const float* wv      = (const float*)d_in[10];
    const float* bv      = (const float*)d_in[11];
    const float* gamma   = (const float*)d_in[12];
    const float* convb_w = (const float*)d_in[13];
    const float* bn2_g   = (const float*)d_in[14];
    const float* bn2_b   = (const float*)d_in[15];
    const float* bn2_m   = (const float*)d_in[16];
    const float* bn2_v   = (const float*)d_in[17];
    const float* bott_w  = (const float*)d_in[18];
    float* out = (float*)d_out;

    float *featA, *featB, *qb, *kb, *ktb, *vb, *vtb, *attb;
    cudaGetSymbolAddress((void**)&featA, g_featA);
    cudaGetSymbolAddress((void**)&featB, g_featB);
    cudaGetSymbolAddress((void**)&qb,    g_q);
    cudaGetSymbolAddress((void**)&kb,    g_k);
    cudaGetSymbolAddress((void**)&ktb,   g_kt);
    cudaGetSymbolAddress((void**)&vb,    g_v);
    cudaGetSymbolAddress((void**)&vtb,   g_vt);
    cudaGetSymbolAddress((void**)&attb,  g_att);

    const int QKV_SMEM = (128*128 + 128*164) * 4;   // 149504 B
    const int OHW_SMEM = (64*68 + 64*132) * 4;      // 51200 B
    cudaFuncSetAttribute(qkv_k, cudaFuncAttributeMaxDynamicSharedMemorySize, QKV_SMEM);
    cudaFuncSetAttribute(oH_k,  cudaFuncAttributeMaxDynamicSharedMemorySize, OHW_SMEM);
    cudaFuncSetAttribute(oW_k,  cudaFuncAttributeMaxDynamicSharedMemorySize, OHW_SMEM);

    // conv1 + BN1 -> featA
    conv3x3_k<<<dim3(2, BB*(CI/8)), 256>>>(x, CIN, nullptr, 0, conva_w,
                                           bn1_g, bn1_b, bn1_m, bn1_v,
                                           featA, CI, 0);

    float* F = featA;
    float* G = featB;
    for (int it = 0; it < 2; it++) {   // recurrence = 2 (fixed by setup_inputs)
        qkv_k<<<dim3(32, BB), 256, QKV_SMEM>>>(F, wq, bq, wk, bk, wv, bv, qb, kb, vb);
        trans_k<<<BB*CQ, 256>>>(kb, ktb);
        trans_k<<<BB*CI, 256>>>(vb, vtb);
        att_k<<<dim3(HH, BB), 256>>>(qb, kb, ktb, attb);
        oH_k<<<dim3(WW, BB), 256, OHW_SMEM>>>(attb, vtb, G);
        oW_k<<<dim3(HH, BB), 256, OHW_SMEM>>>(attb, vb, F, gamma, G);
        float* tmp = F; F = G; G = tmp;
    }

    // convb + BN2 -> G
    conv3x3_k<<<dim3(2, BB*(CI/8)), 256>>>(F, CI, nullptr, 0, convb_w,
                                           bn2_g, bn2_b, bn2_m, bn2_v,
                                           G, CI, 0);
    // bottleneck conv over virtual concat [x(512) | G(128)] + ELU -> out
    conv3x3_k<<<dim3(2, BB*(CIN/8)), 256>>>(x, CIN, G, CI, bott_w,
                                            nullptr, nullptr, nullptr, nullptr,
                                            out, CIN, 1);
}

// round 3
// speedup vs baseline: 6.0412x; 6.0412x over previous
#include <cuda_runtime.h>
#include <cuda_bf16.h>
#include <math.h>
#include <stdint.h>

#define BB 8
#define HH 64
#define WW 64
#define HWSZ 4096
#define CI 128
#define CQ 16
#define CIN 512

// ---------------- scratch buffers (static device allocations) ----------------
__device__ float g_featA[BB*CI*HWSZ];
__device__ float g_featB[BB*CI*HWSZ];
__device__ float g_q [BB*CQ*HWSZ];
__device__ float g_k [BB*CQ*HWSZ];
__device__ float g_kt[BB*CQ*HWSZ];
__device__ float g_v [BB*CI*HWSZ];
__device__ float g_vt[BB*CI*HWSZ];
__device__ float g_att[BB*HH*WW*128];

// padded NHWC bf16 hi/lo feature maps (16B aligned via uint4)
#define XP640_ELEMS (8ULL*66*66*640)
#define XP128_ELEMS (8ULL*66*66*128)
#define WSP_ELEMS   (9ULL*512*640)
__device__ uint4 g_xph4[XP640_ELEMS/8];
__device__ uint4 g_xpl4[XP640_ELEMS/8];
__device__ uint4 g_x2h4[XP128_ELEMS/8];
__device__ uint4 g_x2l4[XP128_ELEMS/8];
__device__ uint4 g_whi4[WSP_ELEMS/8];
__device__ uint4 g_wlo4[WSP_ELEMS/8];

// =====================================================================
// PTX helpers (compute_103-safe: mma.sync / ldmatrix / cp.async only)
// =====================================================================
__device__ __forceinline__ uint32_t smem_u32(const void* p) {
    uint32_t a;
    asm("{ .reg .u64 t; cvta.to.shared.u64 t, %1; cvt.u32.u64 %0, t; }" : "=r"(a) : "l"(p));
    return a;
}
__device__ __forceinline__ void cpa16(uint32_t dst, const void* src) {
    asm volatile("cp.async.cg.shared.global [%0], [%1], 16;" :: "r"(dst), "l"(src) : "memory");
}
__device__ __forceinline__ void cpa_commit() {
    asm volatile("cp.async.commit_group;" ::: "memory");
}
__device__ __forceinline__ void cpa_wait1() {
    asm volatile("cp.async.wait_group 1;" ::: "memory");
}
__device__ __forceinline__ void cpa_wait0() {
    asm volatile("cp.async.wait_group 0;" ::: "memory");
}
__device__ __forceinline__ void ldsm4(uint32_t* r, uint32_t addr) {
    asm volatile("ldmatrix.sync.aligned.m8n8.x4.shared.b16 {%0,%1,%2,%3}, [%4];"
                 : "=r"(r[0]), "=r"(r[1]), "=r"(r[2]), "=r"(r[3]) : "r"(addr));
}
__device__ __forceinline__ void mma16816(float* c, const uint32_t* a, const uint32_t* b) {
    asm volatile(
        "mma.sync.aligned.m16n8k16.row.col.f32.bf16.bf16.f32 "
        "{%0,%1,%2,%3}, {%4,%5,%6,%7}, {%8,%9}, {%0,%1,%2,%3};"
        : "+f"(c[0]), "+f"(c[1]), "+f"(c[2]), "+f"(c[3])
        : "r"(a[0]), "r"(a[1]), "r"(a[2]), "r"(a[3]), "r"(b[0]), "r"(b[1]));
}

// =====================================================================
// prep: NCHW fp32 -> padded NHWC bf16 hi/lo (interior only)
// =====================================================================
__global__ void __launch_bounds__(256) pad_k(
    const float* __restrict__ src, int C,
    __nv_bfloat16* __restrict__ dh, __nv_bfloat16* __restrict__ dl,
    int pitch, int colofs)
{
    __shared__ float s[64][65];
    const int y = blockIdx.x, cbase = blockIdx.y * 64, b = blockIdx.z;
    const int t = threadIdx.x;
    for (int idx = t; idx < 4096; idx += 256) {
        int icl = idx >> 6, x = idx & 63;
        s[icl][x] = src[((size_t)(b*C + cbase + icl)*64 + y)*64 + x];
    }
    __syncthreads();
    for (int idx = t; idx < 4096; idx += 256) {
        int x = idx >> 6, icl = idx & 63;
        float v = s[icl][x];
        __nv_bfloat16 h = __float2bfloat16_rn(v);
        __nv_bfloat16 l = __float2bfloat16_rn(v - __bfloat162float(h));
        size_t o = ((size_t)(b*66 + y + 1)*66 + (x + 1))*pitch + colofs + cbase + icl;
        dh[o] = h; dl[o] = l;
    }
}

__global__ void __launch_bounds__(256) zero_border_k(
    __nv_bfloat16* __restrict__ dh, __nv_bfloat16* __restrict__ dl, int pitch)
{
    const int total = 8 * 260 * pitch;
    for (int idx = blockIdx.x*256 + threadIdx.x; idx < total; idx += gridDim.x*256) {
        int ic = idx % pitch;
        int r  = idx / pitch;
        int b  = r / 260;
        int pos = r % 260;
        int yy, xx;
        if      (pos < 66)  { yy = 0;  xx = pos; }
        else if (pos < 132) { yy = 65; xx = pos - 66; }
        else if (pos < 196) { yy = pos - 132 + 1; xx = 0; }
        else                { yy = pos - 196 + 1; xx = 65; }
        size_t o = ((size_t)(b*66 + yy)*66 + xx)*pitch + ic;
        dh[o] = __float2bfloat16_rn(0.f);
        dl[o] = __float2bfloat16_rn(0.f);
    }
}

// weights: w[oc][ic][3][3] fp32 -> Wh/Wl [tap][oc][ic] bf16
__global__ void __launch_bounds__(256) wprep_k(
    const float* __restrict__ w, int Cout, int Ctot,
    __nv_bfloat16* __restrict__ wh, __nv_bfloat16* __restrict__ wl)
{
    const int total = Cout * Ctot * 9;
    for (int idx = blockIdx.x*256 + threadIdx.x; idx < total; idx += gridDim.x*256) {
        int ic  = idx % Ctot;
        int r   = idx / Ctot;
        int oc  = r % Cout;
        int tap = r / Cout;
        float v = w[(size_t)(oc*Ctot + ic)*9 + tap];
        __nv_bfloat16 h = __float2bfloat16_rn(v);
        __nv_bfloat16 l = __float2bfloat16_rn(v - __bfloat162float(h));
        size_t o = (size_t)(tap*Cout + oc)*Ctot + ic;
        wh[o] = h; wl[o] = l;
    }
}

// =====================================================================
// HMMA implicit-GEMM conv3x3: CTA tile M=128 oc x N=128 px (2 rows),
// warp tile 64x32, K-chunk = (tap, 64 ic), bf16 hi/lo 3-MMA split.
// cp.async double-buffered. Epilogue: mode 0 = BN, mode 1 = ELU(512).
// =====================================================================
#define PITCHB 144            // smem row pitch in bytes (72 bf16) -> conflict-free ldmatrix
#define TILE_B (128*PITCHB)   // 18432 B per tile
#define OFF_AH 0
#define OFF_AL TILE_B
#define OFF_BH (2*TILE_B)
#define OFF_BL (3*TILE_B)
#define BUF_B  (4*TILE_B)     // 73728 B per buffer
#define SM_TOTAL (2*BUF_B)    // 147456 B

__global__ void __launch_bounds__(256, 1) convmma_k(
    const __nv_bfloat16* __restrict__ Xh, const __nv_bfloat16* __restrict__ Xl,
    int pitch, int chunks,
    const __nv_bfloat16* __restrict__ Wh, const __nv_bfloat16* __restrict__ Wl,
    int Ctot, int Cout,
    const float* __restrict__ bn_g, const float* __restrict__ bn_b,
    const float* __restrict__ bn_m, const float* __restrict__ bn_v,
    float* __restrict__ out, int mode)
{
    extern __shared__ __align__(128) char smem[];
    const uint32_t sb = smem_u32(smem);
    const int t = threadIdx.x;
    const int warp = t >> 5, lane = t & 31;
    const int nog = Cout >> 7;
    const int ocg = blockIdx.y % nog;
    const int b   = blockIdx.y / nog;
    const int y0  = blockIdx.x * 2;
    const int ocb = ocg * 128;

    const int q8 = t & 7;     // 16B sector (8 bf16)
    const int r0 = t >> 3;    // base row 0..31

    const int T = chunks * 9;

    // ---- async tile loader: tile idx i -> (chunk, tap) ----
    auto issue_tile = [&](int i) {
        const int c   = i / 9;
        const int tap = i - c*9;
        const int dy  = tap / 3, dx = tap - dy*3;
        const int ic0 = c * 64;
        const uint32_t base = sb + (uint32_t)(i & 1) * BUF_B;
        #pragma unroll
        for (int p = 0; p < 4; p++) {
            const int m = r0 + 32*p;
            const uint32_t so = (uint32_t)(m*PITCHB + q8*16);
            const size_t ga = (size_t)(tap*Cout + ocb + m)*Ctot + ic0 + q8*8;
            cpa16(base + OFF_AH + so, Wh + ga);
            cpa16(base + OFF_AL + so, Wl + ga);
            const int yl = m >> 6, x = m & 63;
            const size_t gb = ((size_t)(b*66 + y0 + yl + dy)*66 + (x + dx))*pitch
                              + ic0 + q8*8;
            cpa16(base + OFF_BH + so, Xh + gb);
            cpa16(base + OFF_BL + so, Xl + gb);
        }
        cpa_commit();
    };

    // ---- accumulators ----
    const int m0 = (warp >> 2) * 64;
    const int n0 = (warp & 3) * 32;
    float acc[4][4][4];
    #pragma unroll
    for (int mi = 0; mi < 4; mi++)
        #pragma unroll
        for (int nj = 0; nj < 4; nj++)
            #pragma unroll
            for (int u = 0; u < 4; u++) acc[mi][nj][u] = 0.f;

    const int arow  = lane & 15;
    const int acolb = ((lane >> 4) << 3) * 2;           // + k0*2 later
    const int brow  = (lane & 7) + ((lane >> 4) << 3);
    const int bcolb = (((lane >> 3) & 1) << 3) * 2;     // + k0*2 later

    issue_tile(0);

    for (int i = 0; i < T; i++) {
        if (i + 1 < T) { issue_tile(i + 1); cpa_wait1(); }
        else           { cpa_wait0(); }
        __syncthreads();

        const uint32_t base = sb + (uint32_t)(i & 1) * BUF_B;
        const uint32_t sAH = base + OFF_AH, sAL = base + OFF_AL;
        const uint32_t sBH = base + OFF_BH, sBL = base + OFF_BL;

        #pragma unroll
        for (int kk = 0; kk < 4; kk++) {
            const int k0b = kk * 32;   // 16 bf16 = 32 bytes
            uint32_t ah[4][4], al[4][4], bh[2][4], bl[2][4];
            #pragma unroll
            for (int mi = 0; mi < 4; mi++) {
                const uint32_t ro = (uint32_t)((m0 + mi*16 + arow) * PITCHB + k0b + acolb);
                ldsm4(ah[mi], sAH + ro);
                ldsm4(al[mi], sAL + ro);
            }
            #pragma unroll
            for (int ni = 0; ni < 2; ni++) {
                const uint32_t ro = (uint32_t)((n0 + ni*16 + brow) * PITCHB + k0b + bcolb);
                ldsm4(bh[ni], sBH + ro);
                ldsm4(bl[ni], sBL + ro);
            }
            #pragma unroll
            for (int mi = 0; mi < 4; mi++)
                #pragma unroll
                for (int nj = 0; nj < 4; nj++) {
                    const uint32_t* bhp = &bh[nj >> 1][(nj & 1) * 2];
                    const uint32_t* blp = &bl[nj >> 1][(nj & 1) * 2];
                    mma16816(acc[mi][nj], ah[mi], bhp);
                    mma16816(acc[mi][nj], ah[mi], blp);
                    mma16816(acc[mi][nj], al[mi], bhp);
                }
        }
        __syncthreads();
    }

    // ---- epilogue ----
    const int g  = lane >> 2;
    const int t2 = (lane & 3) * 2;
    #pragma unroll
    for (int mi = 0; mi < 4; mi++) {
        const int ocA = ocb + m0 + mi*16 + g;
        const int ocB = ocA + 8;
        float scA = 1.f, biA = 0.f, scB = 1.f, biB = 0.f;
        if (mode == 0) {
            scA = bn_g[ocA] * rsqrtf(bn_v[ocA] + 1e-5f);
            biA = bn_b[ocA] - bn_m[ocA] * scA;
            scB = bn_g[ocB] * rsqrtf(bn_v[ocB] + 1e-5f);
            biB = bn_b[ocB] - bn_m[ocB] * scB;
        }
        #pragma unroll
        for (int nj = 0; nj < 4; nj++) {
            const int n  = n0 + nj*8 + t2;
            const int yl = n >> 6, x = n & 63;
            float v0 = acc[mi][nj][0], v1 = acc[mi][nj][1];
            float v2 = acc[mi][nj][2], v3 = acc[mi][nj][3];
            if (mode == 0) {
                v0 = v0*scA + biA; v1 = v1*scA + biA;
                v2 = v2*scB + biB; v3 = v3*scB + biB;
            } else {
                if (v0 <= 0.f) v0 = 512.0f * expm1f(v0);
                if (v1 <= 0.f) v1 = 512.0f * expm1f(v1);
                if (v2 <= 0.f) v2 = 512.0f * expm1f(v2);
                if (v3 <= 0.f) v3 = 512.0f * expm1f(v3);
            }
            *(float2*)&out[((size_t)(b*Cout + ocA)*64 + y0 + yl)*64 + x] = make_float2(v0, v1);
            *(float2*)&out[((size_t)(b*Cout + ocB)*64 + y0 + yl)*64 + x] = make_float2(v2, v3);
        }
    }
}

// =====================================================================
// attention kernels (fp32 path)
// =====================================================================
__global__ void __launch_bounds__(256) qkv_k(
    const float* __restrict__ feat,
    const float* __restrict__ wq, const float* __restrict__ bq,
    const float* __restrict__ wk, const float* __restrict__ bk,
    const float* __restrict__ wv, const float* __restrict__ bv,
    float* __restrict__ q, float* __restrict__ k, float* __restrict__ v)
{
    extern __shared__ __align__(16) float sm[];
    float* s_in = sm;               // [128 ic][128 px]
    float* s_w  = sm + 128*128;     // [128 ic][pitch 164]

    const int t   = threadIdx.x;
    const int pxb = blockIdx.x * 128;
    const int b   = blockIdx.y;

    const float4* f4 = (const float4*)(feat + (size_t)b*CI*HWSZ);
    for (int idx = t; idx < 128*32; idx += 256) {
        int ic = idx >> 5, p4 = idx & 31;
        ((float4*)s_in)[ic*32 + p4] = f4[ic*(HWSZ/4) + (pxb >> 2) + p4];
    }
    for (int idx = t; idx < 16*128;  idx += 256) { int oc = idx >> 7, ic = idx & 127; s_w[ic*164 + oc]       = wq[idx]; }
    for (int idx = t; idx < 16*128;  idx += 256) { int oc = idx >> 7, ic = idx & 127; s_w[ic*164 + 16 + oc]  = wk[idx]; }
    for (int idx = t; idx < 128*128; idx += 256) { int oc = idx >> 7, ic = idx & 127; s_w[ic*164 + 32 + oc]  = wv[idx]; }
    __syncthreads();

    const int l   = t & 31;
    const int oc0 = (t >> 5) * 20;

    float acc[20][4];
    #pragma unroll
    for (int j = 0; j < 20; j++)
        #pragma unroll
        for (int i = 0; i < 4; i++) acc[j][i] = 0.f;

    for (int ic = 0; ic < 128; ic++) {
        float4 x4 = ((const float4*)s_in)[ic*32 + l];
        const float* wr = s_w + ic*164 + oc0;
        #pragma unroll
        for (int j = 0; j < 5; j++) {
            float4 w4 = *(const float4*)(wr + 4*j);
            acc[4*j+0][0] += w4.x * x4.x; acc[4*j+0][1] += w4.x * x4.y;
            acc[4*j+0][2] += w4.x * x4.z; acc[4*j+0][3] += w4.x * x4.w;
            acc[4*j+1][0] += w4.y * x4.x; acc[4*j+1][1] += w4.y * x4.y;
            acc[4*j+1][2] += w4.y * x4.z; acc[4*j+1][3] += w4.y * x4.w;
            acc[4*j+2][0] += w4.z * x4.x; acc[4*j+2][1] += w4.z * x4.y;
            acc[4*j+2][2] += w4.z * x4.z; acc[4*j+2][3] += w4.z * x4.w;
            acc[4*j+3][0] += w4.w * x4.x; acc[4*j+3][1] += w4.w * x4.y;
            acc[4*j+3][2] += w4.w * x4.z; acc[4*j+3][3] += w4.w * x4.w;
        }
    }

    #pragma unroll
    for (int j = 0; j < 20; j++) {
        const int oc = oc0 + j;
        float bias; float* dst; int o; int C;
        if (oc < 16)      { bias = bq[oc];      dst = q; o = oc;      C = CQ; }
        else if (oc < 32) { bias = bk[oc - 16]; dst = k; o = oc - 16; C = CQ; }
        else              { bias = bv[oc - 32]; dst = v; o = oc - 32; C = CI; }
        *(float4*)&dst[((size_t)b*C + o)*HWSZ + pxb + l*4] =
            make_float4(acc[j][0] + bias, acc[j][1] + bias,
                        acc[j][2] + bias, acc[j][3] + bias);
    }
}

__global__ void __launch_bounds__(256) trans_k(const float* __restrict__ in,
                                               float* __restrict__ out)
{
    __shared__ float s[64][65];
    const float* src = in  + (size_t)blockIdx.x * 4096;
    float*       dst = out + (size_t)blockIdx.x * 4096;
    for (int idx = threadIdx.x; idx < 4096; idx += 256)
        s[idx >> 6][idx & 63] = src[idx];
    __syncthreads();
    for (int idx = threadIdx.x; idx < 4096; idx += 256)
        dst[idx] = s[idx & 63][idx >> 6];
}

__global__ void __launch_bounds__(256) att_k(
    const float* __restrict__ q, const float* __restrict__ k,
    const float* __restrict__ kt, float* __restrict__ att)
{
    __shared__ float qs[16*64];
    __shared__ float ks[16*64];
    __shared__ float E[64*128];

    const int t = threadIdx.x;
    const int h = blockIdx.x, b = blockIdx.y;

    for (int idx = t; idx < 1024; idx += 256) {
        int c = idx >> 6, w = idx & 63;
        qs[idx] = q[((b*CQ + c)*HH + h)*WW + w];
        ks[idx] = k[((b*CQ + c)*HH + h)*WW + w];
    }
    __syncthreads();

    for (int idx = t; idx < 2048; idx += 256) {
        const int w  = idx >> 5;
        const int j4 = idx & 31;
        float4 e = make_float4(0.f, 0.f, 0.f, 0.f);
        if (j4 < 16) {
            for (int c = 0; c < 16; c++) {
                float qq = qs[c*64 + w];
                float4 kv = ((const float4*)kt)[((b*CQ + c)*WW + w)*16 + j4];
                e.x += qq * kv.x; e.y += qq * kv.y; e.z += qq * kv.z; e.w += qq * kv.w;
            }
            if ((h >> 2) == j4) ((float*)&e)[h & 3] = -INFINITY;
        } else {
            for (int c = 0; c < 16; c++) {
                float qq = qs[c*64 + w];
                float4 kv = ((const float4*)ks)[c*16 + (j4 - 16)];
                e.x += qq * kv.x; e.y += qq * kv.y; e.z += qq * kv.z; e.w += qq * kv.w;
            }
        }
        ((float4*)E)[w*32 + j4] = e;
    }
    __syncthreads();

    const int lane = t & 31, wid = t >> 5;
    for (int r = 0; r < 8; r++) {
        const int w = wid*8 + r;
        float v0 = E[w*128 + lane],      v1 = E[w*128 + lane + 32];
        float v2 = E[w*128 + lane + 64], v3 = E[w*128 + lane + 96];
        float m = fmaxf(fmaxf(v0, v1), fmaxf(v2, v3));
        #pragma unroll
        for (int s = 16; s; s >>= 1) m = fmaxf(m, __shfl_xor_sync(0xffffffffu, m, s));
        float e0 = expf(v0 - m), e1 = expf(v1 - m), e2 = expf(v2 - m), e3 = expf(v3 - m);
        float sum = e0 + e1 + e2 + e3;
        #pragma unroll
        for (int s = 16; s; s >>= 1) sum += __shfl_xor_sync(0xffffffffu, sum, s);
        float inv = 1.f / sum;
        float* dst = att + (size_t)((b*HH + h)*WW + w)*128;
        dst[lane] = e0*inv; dst[lane+32] = e1*inv; dst[lane+64] = e2*inv; dst[lane+96] = e3*inv;
    }
}

__global__ void __launch_bounds__(256) oH_k(
    const float* __restrict__ att, const float* __restrict__ vt,
    float* __restrict__ outb)
{
    extern __shared__ __align__(16) float sm[];
    float* As = sm;
    float* Vs = sm + 64*68;

    const int t = threadIdx.x;
    const int w = blockIdx.x, b = blockIdx.y;

    for (int idx = t; idx < 4096; idx += 256) {
        int hh = idx >> 6, g = idx & 63;
        As[g*68 + hh] = att[(size_t)((b*HH + hh)*WW + w)*128 + g];
    }
    for (int idx = t; idx < 8192; idx += 256) {
        int c = idx >> 6, g = idx & 63;
        Vs[g*132 + c] = vt[((b*CI + c)*WW + w)*HH + g];
    }
    __syncthreads();

    const int c0 = (t & 31) * 4;
    const int h0 = (t >> 5) * 8;
    float acc[8][4];
    #pragma unroll
    for (int i = 0; i < 8; i++)
        #pragma unroll
        for (int j = 0; j < 4; j++) acc[i][j] = 0.f;

    for (int g = 0; g < 64; g++) {
        float4 v4 = *(const float4*)&Vs[g*132 + c0];
        #pragma unroll
        for (int hi = 0; hi < 8; hi++) {
            float av = As[g*68 + h0 + hi];
            acc[hi][0] += av * v4.x; acc[hi][1] += av * v4.y;
            acc[hi][2] += av * v4.z; acc[hi][3] += av * v4.w;
        }
    }
    #pragma unroll
    for (int hi = 0; hi < 8; hi++)
        #pragma unroll
        for (int ci = 0; ci < 4; ci++)
            outb[((b*CI + c0 + ci)*HH + h0 + hi)*WW + w] = acc[hi][ci];
}

__global__ void __launch_bounds__(256) oW_k(
    const float* __restrict__ att, const float* __restrict__ v,
    const float* __restrict__ feat, const float* __restrict__ gamma,
    float* __restrict__ outb)
{
    extern __shared__ __align__(16) float sm[];
    float* Aw = sm;
    float* Ws = sm + 64*68;

    const int t = threadIdx.x;
    const int h = blockIdx.x, b = blockIdx.y;

    for (int idx = t; idx < 4096; idx += 256) {
        int w = idx >> 6, wp = idx & 63;
        Aw[wp*68 + w] = att[(size_t)((b*HH + h)*WW + w)*128 + 64 + wp];
    }
    for (int idx = t; idx < 8192; idx += 256) {
        int c = idx >> 6, wp = idx & 63;
        Ws[wp*132 + c] = v[((b*CI + c)*HH + h)*WW + wp];
    }
    __syncthreads();

    const int c0 = (t & 31) * 4;
    const int w0 = (t >> 5) * 8;
    float acc[8][4];
    #pragma unroll
    for (int i = 0; i < 8; i++)
        #pragma unroll
        for (int j = 0; j < 4; j++) acc[i][j] = 0.f;

    for (int wp = 0; wp < 64; wp++) {
        float4 v4 = *(const float4*)&Ws[wp*132 + c0];
        #pragma unroll
        for (int wi = 0; wi < 8; wi++) {
            float av = Aw[wp*68 + w0 + wi];
            acc[wi][0] += av * v4.x; acc[wi][1] += av * v4.y;
            acc[wi][2] += av * v4.z; acc[wi][3] += av * v4.w;
        }
    }

    const float g = gamma[0];
    #pragma unroll
    for (int ci = 0; ci < 4; ci++) {
        const int base = ((b*CI + c0 + ci)*HH + h)*WW + w0;
        float4 f0 = *(const float4*)&feat[base];
        float4 f1 = *(const float4*)&feat[base + 4];
        float4 o0 = *(const float4*)&outb[base];
        float4 o1 = *(const float4*)&outb[base + 4];
        float4 r0 = make_float4(f0.x + g*(o0.x + acc[0][ci]),
                                f0.y + g*(o0.y + acc[1][ci]),
                                f0.z + g*(o0.z + acc[2][ci]),
                                f0.w + g*(o0.w + acc[3][ci]));
        float4 r1 = make_float4(f1.x + g*(o1.x + acc[4][ci]),
                                f1.y + g*(o1.y + acc[5][ci]),
                                f1.z + g*(o1.z + acc[6][ci]),
                                f1.w + g*(o1.w + acc[7][ci]));
        *(float4*)&outb[base]     = r0;
        *(float4*)&outb[base + 4] = r1;
    }
}

// =====================================================================
extern "C" void kernel_launch(void* const* d_in, const int* in_sizes, int n_in,
                              void* d_out, int out_size)
{
    (void)in_sizes; (void)n_in; (void)out_size;
    const float* x       = (const float*)d_in[0];
    const float* conva_w = (const float*)d_in[1];
    const float* bn1_g   = (const float*)d_in[2];
    const float* bn1_b   = (const float*)d_in[3];
    const float* bn1_m   = (const float*)d_in[4];
    const float* bn1_v   = (const float*)d_in[5];
    const float* wq      = (const float*)d_in[6];
    const float* bq      = (const float*)d_in[7];
    const float* wk      = (const float*)d_in[8];
    const float* bk      = (const float*)d_in[9];
    const float* wv      = (const float*)d_in[10];
    const float* bv      = (const float*)d_in[11];
    const float* gamma   = (const float*)d_in[12];
    const float* convb_w = (const float*)d_in[13];
    const float* bn2_g   = (const float*)d_in[14];
    const float* bn2_b   = (const float*)d_in[15];
    const float* bn2_m   = (const float*)d_in[16];
    const float* bn2_v   = (const float*)d_in[17];
    const float* bott_w  = (const float*)d_in[18];
    float* out = (float*)d_out;

    float *featA, *featB, *qb, *kb, *ktb, *vb, *vtb, *attb;
    cudaGetSymbolAddress((void**)&featA, g_featA);
    cudaGetSymbolAddress((void**)&featB, g_featB);
    cudaGetSymbolAddress((void**)&qb,    g_q);
    cudaGetSymbolAddress((void**)&kb,    g_k);
    cudaGetSymbolAddress((void**)&ktb,   g_kt);
    cudaGetSymbolAddress((void**)&vb,    g_v);
    cudaGetSymbolAddress((void**)&vtb,   g_vt);
    cudaGetSymbolAddress((void**)&attb,  g_att);

    __nv_bfloat16 *xph, *xpl, *x2h, *x2l, *whi, *wlo;
    cudaGetSymbolAddress((void**)&xph, g_xph4);
    cudaGetSymbolAddress((void**)&xpl, g_xpl4);
    cudaGetSymbolAddress((void**)&x2h, g_x2h4);
    cudaGetSymbolAddress((void**)&x2l, g_x2l4);
    cudaGetSymbolAddress((void**)&whi, g_whi4);
    cudaGetSymbolAddress((void**)&wlo, g_wlo4);

    const int QKV_SMEM = (128*128 + 128*164) * 4;
    const int OHW_SMEM = (64*68 + 64*132) * 4;
    cudaFuncSetAttribute(qkv_k,     cudaFuncAttributeMaxDynamicSharedMemorySize, QKV_SMEM);
    cudaFuncSetAttribute(oH_k,      cudaFuncAttributeMaxDynamicSharedMemorySize, OHW_SMEM);
    cudaFuncSetAttribute(oW_k,      cudaFuncAttributeMaxDynamicSharedMemorySize, OHW_SMEM);
    cudaFuncSetAttribute(convmma_k, cudaFuncAttributeMaxDynamicSharedMemorySize, SM_TOTAL);

    // ---- conv1 (512 -> 128) + BN1 ----
    wprep_k<<<512, 256>>>(conva_w, CI, CIN, whi, wlo);
    pad_k<<<dim3(64, CIN/64, BB), 256>>>(x, CIN, xph, xpl, 640, 0);
    zero_border_k<<<1024, 256>>>(xph, xpl, 640);
    convmma_k<<<dim3(32, BB), 256, SM_TOTAL>>>(xph, xpl, 640, CIN/64,
                                               whi, wlo, CIN, CI,
                                               bn1_g, bn1_b, bn1_m, bn1_v,
                                               featA, 0);

    // ---- criss-cross attention x2 ----
    float* F = featA;
    float* G = featB;
    for (int it = 0; it < 2; it++) {
        qkv_k<<<dim3(32, BB), 256, QKV_SMEM>>>(F, wq, bq, wk, bk, wv, bv, qb, kb, vb);
        trans_k<<<BB*CQ, 256>>>(kb, ktb);
        trans_k<<<BB*CI, 256>>>(vb, vtb);
        att_k<<<dim3(HH, BB), 256>>>(qb, kb, ktb, attb);
        oH_k<<<dim3(WW, BB), 256, OHW_SMEM>>>(attb, vtb, G);
        oW_k<<<dim3(HH, BB), 256, OHW_SMEM>>>(attb, vb, F, gamma, G);
        float* tmp = F; F = G; G = tmp;
    }
    // after 2 iters: F = featA, G = featB

    // ---- convb (128 -> 128) + BN2 ----
    wprep_k<<<576, 256>>>(convb_w, CI, CI, whi, wlo);
    pad_k<<<dim3(64, CI/64, BB), 256>>>(F, CI, x2h, x2l, 128, 0);
    zero_border_k<<<1024, 256>>>(x2h, x2l, 128);
    convmma_k<<<dim3(32, BB), 256, SM_TOTAL>>>(x2h, x2l, 128, CI/64,
                                               whi, wlo, CI, CI,
                                               bn2_g, bn2_b, bn2_m, bn2_v,
                                               G, 0);

    // ---- bottleneck conv (concat 512+128 -> 512) + ELU ----
    pad_k<<<dim3(64, CI/64, BB), 256>>>(G, CI, xph, xpl, 640, CIN);
    wprep_k<<<4096, 256>>>(bott_w, CIN, CIN + CI, whi, wlo);
    convmma_k<<<dim3(32, BB*(CIN/128)), 256, SM_TOTAL>>>(xph, xpl, 640, (CIN + CI)/64,
                                                         whi, wlo, CIN + CI, CIN,
                                                         nullptr, nullptr, nullptr, nullptr,
                                                         out, 1);
}

// round 4
// speedup vs baseline: 7.7861x; 1.2888x over previous
#include <cuda_runtime.h>
#include <cuda_fp16.h>
#include <math.h>
#include <stdint.h>

#define BB 8
#define HH 64
#define WW 64
#define HWSZ 4096
#define CI 128
#define CQ 16
#define CIN 512

// ---------------- scratch buffers (static device allocations) ----------------
__device__ float g_featA[BB*CI*HWSZ];
__device__ float g_featB[BB*CI*HWSZ];
__device__ float g_q [BB*CQ*HWSZ];
__device__ float g_k [BB*CQ*HWSZ];
__device__ float g_kt[BB*CQ*HWSZ];
__device__ float g_v [BB*CI*HWSZ];
__device__ float g_vt[BB*CI*HWSZ];
__device__ float g_att[BB*HH*WW*128];

// padded NHWC fp16 hi/lo feature maps (16B aligned via uint4)
#define XP640_ELEMS (8ULL*66*66*640)
#define XP128_ELEMS (8ULL*66*66*128)
#define WSP_ELEMS   (9ULL*512*640)
__device__ uint4 g_xph4[XP640_ELEMS/8];
__device__ uint4 g_xpl4[XP640_ELEMS/8];
__device__ uint4 g_x2h4[XP128_ELEMS/8];
__device__ uint4 g_x2l4[XP128_ELEMS/8];
__device__ uint4 g_whi4[WSP_ELEMS/8];

// =====================================================================
// PTX helpers (compute_103-safe: mma.sync / ldmatrix / cp.async only)
// =====================================================================
__device__ __forceinline__ uint32_t smem_u32(const void* p) {
    uint32_t a;
    asm("{ .reg .u64 t; cvta.to.shared.u64 t, %1; cvt.u32.u64 %0, t; }" : "=r"(a) : "l"(p));
    return a;
}
__device__ __forceinline__ void cpa16(uint32_t dst, const void* src) {
    asm volatile("cp.async.cg.shared.global [%0], [%1], 16;" :: "r"(dst), "l"(src) : "memory");
}
__device__ __forceinline__ void cpa_commit() {
    asm volatile("cp.async.commit_group;" ::: "memory");
}
__device__ __forceinline__ void cpa_wait0() {
    asm volatile("cp.async.wait_group 0;" ::: "memory");
}
__device__ __forceinline__ void ldsm4(uint32_t* r, uint32_t addr) {
    asm volatile("ldmatrix.sync.aligned.m8n8.x4.shared.b16 {%0,%1,%2,%3}, [%4];"
                 : "=r"(r[0]), "=r"(r[1]), "=r"(r[2]), "=r"(r[3]) : "r"(addr));
}
__device__ __forceinline__ void mma16816(float* c, const uint32_t* a, const uint32_t* b) {
    asm volatile(
        "mma.sync.aligned.m16n8k16.row.col.f32.f16.f16.f32 "
        "{%0,%1,%2,%3}, {%4,%5,%6,%7}, {%8,%9}, {%0,%1,%2,%3};"
        : "+f"(c[0]), "+f"(c[1]), "+f"(c[2]), "+f"(c[3])
        : "r"(a[0]), "r"(a[1]), "r"(a[2]), "r"(a[3]), "r"(b[0]), "r"(b[1]));
}

// =====================================================================
// prep: NCHW fp32 -> padded NHWC fp16 hi/lo (interior only)
// =====================================================================
__global__ void __launch_bounds__(256) pad_k(
    const float* __restrict__ src, int C,
    __half* __restrict__ dh, __half* __restrict__ dl,
    int pitch, int colofs)
{
    __shared__ float s[64][65];
    const int y = blockIdx.x, cbase = blockIdx.y * 64, b = blockIdx.z;
    const int t = threadIdx.x;
    for (int idx = t; idx < 4096; idx += 256) {
        int icl = idx >> 6, x = idx & 63;
        s[icl][x] = src[((size_t)(b*C + cbase + icl)*64 + y)*64 + x];
    }
    __syncthreads();
    for (int idx = t; idx < 4096; idx += 256) {
        int x = idx >> 6, icl = idx & 63;
        float v = s[icl][x];
        __half h = __float2half_rn(v);
        __half l = __float2half_rn(v - __half2float(h));
        size_t o = ((size_t)(b*66 + y + 1)*66 + (x + 1))*pitch + colofs + cbase + icl;
        dh[o] = h; dl[o] = l;
    }
}

__global__ void __launch_bounds__(256) zero_border_k(
    __half* __restrict__ dh, __half* __restrict__ dl, int pitch)
{
    const int total = 8 * 260 * pitch;
    for (int idx = blockIdx.x*256 + threadIdx.x; idx < total; idx += gridDim.x*256) {
        int ic = idx % pitch;
        int r  = idx / pitch;
        int b  = r / 260;
        int pos = r % 260;
        int yy, xx;
        if      (pos < 66)  { yy = 0;  xx = pos; }
        else if (pos < 132) { yy = 65; xx = pos - 66; }
        else if (pos < 196) { yy = pos - 132 + 1; xx = 0; }
        else                { yy = pos - 196 + 1; xx = 65; }
        size_t o = ((size_t)(b*66 + yy)*66 + xx)*pitch + ic;
        dh[o] = __float2half_rn(0.f);
        dl[o] = __float2half_rn(0.f);
    }
}

// weights: w[oc][ic][3][3] fp32 -> Wh [tap][oc][ic] fp16 (single)
__global__ void __launch_bounds__(256) wprep_k(
    const float* __restrict__ w, int Cout, int Ctot,
    __half* __restrict__ wh)
{
    const int total = Cout * Ctot * 9;
    for (int idx = blockIdx.x*256 + threadIdx.x; idx < total; idx += gridDim.x*256) {
        int ic  = idx % Ctot;
        int r   = idx / Ctot;
        int oc  = r % Cout;
        int tap = r / Cout;
        float v = w[(size_t)(oc*Ctot + ic)*9 + tap];
        wh[(size_t)(tap*Cout + oc)*Ctot + ic] = __float2half_rn(v);
    }
}

// =====================================================================
// HMMA implicit-GEMM conv3x3: CTA tile M=128 oc x N=128 px (2 rows),
// warp tile 64x32, K-chunk = (tap, 64 ic).
// fp16: W single, X hi/lo split -> 2 MMAs per fragment pair.
// cp.async double-buffered, single __syncthreads per tile.
// Epilogue: mode 0 = BN, mode 1 = ELU(512).
// =====================================================================
#define PITCHB 144            // smem row pitch in bytes (72 fp16) -> conflict-free ldmatrix
#define TILE_B (128*PITCHB)   // 18432 B per tile
#define OFF_A  0
#define OFF_BH TILE_B
#define OFF_BL (2*TILE_B)
#define BUF_B  (3*TILE_B)     // 55296 B per buffer
#define SM_TOTAL (2*BUF_B)    // 110592 B

__global__ void __launch_bounds__(256, 1) convmma_k(
    const __half* __restrict__ Xh, const __half* __restrict__ Xl,
    int pitch, int chunks,
    const __half* __restrict__ Wh,
    int Ctot, int Cout,
    const float* __restrict__ bn_g, const float* __restrict__ bn_b,
    const float* __restrict__ bn_m, const float* __restrict__ bn_v,
    float* __restrict__ out, int mode)
{
    extern __shared__ __align__(128) char smem[];
    const uint32_t sb = smem_u32(smem);
    const int t = threadIdx.x;
    const int warp = t >> 5, lane = t & 31;
    const int nog = Cout >> 7;
    const int ocg = blockIdx.y % nog;
    const int b   = blockIdx.y / nog;
    const int y0  = blockIdx.x * 2;
    const int ocb = ocg * 128;

    const int q8 = t & 7;     // 16B sector (8 fp16)
    const int r0 = t >> 3;    // base row 0..31

    const int T = chunks * 9;

    // ---- async tile loader: tile idx i -> (chunk, tap) ----
    auto issue_tile = [&](int i) {
        const int c   = i / 9;
        const int tap = i - c*9;
        const int dy  = tap / 3, dx = tap - dy*3;
        const int ic0 = c * 64;
        const uint32_t base = sb + (uint32_t)(i & 1) * BUF_B;
        #pragma unroll
        for (int p = 0; p < 4; p++) {
            const int m = r0 + 32*p;
            const uint32_t so = (uint32_t)(m*PITCHB + q8*16);
            const size_t ga = (size_t)(tap*Cout + ocb + m)*Ctot + ic0 + q8*8;
            cpa16(base + OFF_A + so, Wh + ga);
            const int yl = m >> 6, x = m & 63;
            const size_t gb = ((size_t)(b*66 + y0 + yl + dy)*66 + (x + dx))*pitch
                              + ic0 + q8*8;
            cpa16(base + OFF_BH + so, Xh + gb);
            cpa16(base + OFF_BL + so, Xl + gb);
        }
        cpa_commit();
    };

    // ---- accumulators ----
    const int m0 = (warp >> 2) * 64;
    const int n0 = (warp & 3) * 32;
    float acc[4][4][4];
    #pragma unroll
    for (int mi = 0; mi < 4; mi++)
        #pragma unroll
        for (int nj = 0; nj < 4; nj++)
            #pragma unroll
            for (int u = 0; u < 4; u++) acc[mi][nj][u] = 0.f;

    const int arow  = lane & 15;
    const int acolb = ((lane >> 4) << 3) * 2;           // + k0 bytes later
    const int brow  = (lane & 7) + ((lane >> 4) << 3);
    const int bcolb = (((lane >> 3) & 1) << 3) * 2;     // + k0 bytes later

    issue_tile(0);

    for (int i = 0; i < T; i++) {
        cpa_wait0();           // tile i resident (only group i outstanding)
        __syncthreads();       // all warps done with compute(i-1) -> buffer (i+1)&1 free
        if (i + 1 < T) issue_tile(i + 1);   // overlaps compute below

        const uint32_t base = sb + (uint32_t)(i & 1) * BUF_B;
        const uint32_t sA  = base + OFF_A;
        const uint32_t sBH = base + OFF_BH, sBL = base + OFF_BL;

        #pragma unroll
        for (int kk = 0; kk < 4; kk++) {
            const int k0b = kk * 32;   // 16 fp16 = 32 bytes
            uint32_t a[4][4], bh[2][4], bl[2][4];
            #pragma unroll
            for (int mi = 0; mi < 4; mi++) {
                const uint32_t ro = (uint32_t)((m0 + mi*16 + arow) * PITCHB + k0b + acolb);
                ldsm4(a[mi], sA + ro);
            }
            #pragma unroll
            for (int ni = 0; ni < 2; ni++) {
                const uint32_t ro = (uint32_t)((n0 + ni*16 + brow) * PITCHB + k0b + bcolb);
                ldsm4(bh[ni], sBH + ro);
                ldsm4(bl[ni], sBL + ro);
            }
            #pragma unroll
            for (int mi = 0; mi < 4; mi++)
                #pragma unroll
                for (int nj = 0; nj < 4; nj++) {
                    const uint32_t* bhp = &bh[nj >> 1][(nj & 1) * 2];
                    const uint32_t* blp = &bl[nj >> 1][(nj & 1) * 2];
                    mma16816(acc[mi][nj], a[mi], bhp);
                    mma16816(acc[mi][nj], a[mi], blp);
                }
        }
    }

    // ---- epilogue ----
    const int g  = lane >> 2;
    const int t2 = (lane & 3) * 2;
    #pragma unroll
    for (int mi = 0; mi < 4; mi++) {
        const int ocA = ocb + m0 + mi*16 + g;
        const int ocB = ocA + 8;
        float scA = 1.f, biA = 0.f, scB = 1.f, biB = 0.f;
        if (mode == 0) {
            scA = bn_g[ocA] * rsqrtf(bn_v[ocA] + 1e-5f);
            biA = bn_b[ocA] - bn_m[ocA] * scA;
            scB = bn_g[ocB] * rsqrtf(bn_v[ocB] + 1e-5f);
            biB = bn_b[ocB] - bn_m[ocB] * scB;
        }
        #pragma unroll
        for (int nj = 0; nj < 4; nj++) {
            const int n  = n0 + nj*8 + t2;
            const int yl = n >> 6, x = n & 63;
            float v0 = acc[mi][nj][0], v1 = acc[mi][nj][1];
            float v2 = acc[mi][nj][2], v3 = acc[mi][nj][3];
            if (mode == 0) {
                v0 = v0*scA + biA; v1 = v1*scA + biA;
                v2 = v2*scB + biB; v3 = v3*scB + biB;
            } else {
                if (v0 <= 0.f) v0 = 512.0f * expm1f(v0);
                if (v1 <= 0.f) v1 = 512.0f * expm1f(v1);
                if (v2 <= 0.f) v2 = 512.0f * expm1f(v2);
                if (v3 <= 0.f) v3 = 512.0f * expm1f(v3);
            }
            *(float2*)&out[((size_t)(b*Cout + ocA)*64 + y0 + yl)*64 + x] = make_float2(v0, v1);
            *(float2*)&out[((size_t)(b*Cout + ocB)*64 + y0 + yl)*64 + x] = make_float2(v2, v3);
        }
    }
}

// =====================================================================
// attention kernels (fp32 path)
// =====================================================================
__global__ void __launch_bounds__(256) qkv_k(
    const float* __restrict__ feat,
    const float* __restrict__ wq, const float* __restrict__ bq,
    const float* __restrict__ wk, const float* __restrict__ bk,
    const float* __restrict__ wv, const float* __restrict__ bv,
    float* __restrict__ q, float* __restrict__ k, float* __restrict__ v)
{
    extern __shared__ __align__(16) float sm[];
    float* s_in = sm;               // [128 ic][128 px]
    float* s_w  = sm + 128*128;     // [128 ic][pitch 164]

    const int t   = threadIdx.x;
    const int pxb = blockIdx.x * 128;
    const int b   = blockIdx.y;

    const float4* f4 = (const float4*)(feat + (size_t)b*CI*HWSZ);
    for (int idx = t; idx < 128*32; idx += 256) {
        int ic = idx >> 5, p4 = idx & 31;
        ((float4*)s_in)[ic*32 + p4] = f4[ic*(HWSZ/4) + (pxb >> 2) + p4];
    }
    for (int idx = t; idx < 16*128;  idx += 256) { int oc = idx >> 7, ic = idx & 127; s_w[ic*164 + oc]       = wq[idx]; }
    for (int idx = t; idx < 16*128;  idx += 256) { int oc = idx >> 7, ic = idx & 127; s_w[ic*164 + 16 + oc]  = wk[idx]; }
    for (int idx = t; idx < 128*128; idx += 256) { int oc = idx >> 7, ic = idx & 127; s_w[ic*164 + 32 + oc]  = wv[idx]; }
    __syncthreads();

    const int l   = t & 31;
    const int oc0 = (t >> 5) * 20;

    float acc[20][4];
    #pragma unroll
    for (int j = 0; j < 20; j++)
        #pragma unroll
        for (int i = 0; i < 4; i++) acc[j][i] = 0.f;

    for (int ic = 0; ic < 128; ic++) {
        float4 x4 = ((const float4*)s_in)[ic*32 + l];
        const float* wr = s_w + ic*164 + oc0;
        #pragma unroll
        for (int j = 0; j < 5; j++) {
            float4 w4 = *(const float4*)(wr + 4*j);
            acc[4*j+0][0] += w4.x * x4.x; acc[4*j+0][1] += w4.x * x4.y;
            acc[4*j+0][2] += w4.x * x4.z; acc[4*j+0][3] += w4.x * x4.w;
            acc[4*j+1][0] += w4.y * x4.x; acc[4*j+1][1] += w4.y * x4.y;
            acc[4*j+1][2] += w4.y * x4.z; acc[4*j+1][3] += w4.y * x4.w;
            acc[4*j+2][0] += w4.z * x4.x; acc[4*j+2][1] += w4.z * x4.y;
            acc[4*j+2][2] += w4.z * x4.z; acc[4*j+2][3] += w4.z * x4.w;
            acc[4*j+3][0] += w4.w * x4.x; acc[4*j+3][1] += w4.w * x4.y;
            acc[4*j+3][2] += w4.w * x4.z; acc[4*j+3][3] += w4.w * x4.w;
        }
    }

    #pragma unroll
    for (int j = 0; j < 20; j++) {
        const int oc = oc0 + j;
        float bias; float* dst; int o; int C;
        if (oc < 16)      { bias = bq[oc];      dst = q; o = oc;      C = CQ; }
        else if (oc < 32) { bias = bk[oc - 16]; dst = k; o = oc - 16; C = CQ; }
        else              { bias = bv[oc - 32]; dst = v; o = oc - 32; C = CI; }
        *(float4*)&dst[((size_t)b*C + o)*HWSZ + pxb + l*4] =
            make_float4(acc[j][0] + bias, acc[j][1] + bias,
                        acc[j][2] + bias, acc[j][3] + bias);
    }
}

__global__ void __launch_bounds__(256) trans_k(const float* __restrict__ in,
                                               float* __restrict__ out)
{
    __shared__ float s[64][65];
    const float* src = in  + (size_t)blockIdx.x * 4096;
    float*       dst = out + (size_t)blockIdx.x * 4096;
    for (int idx = threadIdx.x; idx < 4096; idx += 256)
        s[idx >> 6][idx & 63] = src[idx];
    __syncthreads();
    for (int idx = threadIdx.x; idx < 4096; idx += 256)
        dst[idx] = s[idx & 63][idx >> 6];
}

__global__ void __launch_bounds__(256) att_k(
    const float* __restrict__ q, const float* __restrict__ k,
    const float* __restrict__ kt, float* __restrict__ att)
{
    __shared__ float qs[16*64];
    __shared__ float ks[16*64];
    __shared__ float E[64*128];

    const int t = threadIdx.x;
    const int h = blockIdx.x, b = blockIdx.y;

    for (int idx = t; idx < 1024; idx += 256) {
        int c = idx >> 6, w = idx & 63;
        qs[idx] = q[((b*CQ + c)*HH + h)*WW + w];
        ks[idx] = k[((b*CQ + c)*HH + h)*WW + w];
    }
    __syncthreads();

    for (int idx = t; idx < 2048; idx += 256) {
        const int w  = idx >> 5;
        const int j4 = idx & 31;
        float4 e = make_float4(0.f, 0.f, 0.f, 0.f);
        if (j4 < 16) {
            for (int c = 0; c < 16; c++) {
                float qq = qs[c*64 + w];
                float4 kv = ((const float4*)kt)[((b*CQ + c)*WW + w)*16 + j4];
                e.x += qq * kv.x; e.y += qq * kv.y; e.z += qq * kv.z; e.w += qq * kv.w;
            }
            if ((h >> 2) == j4) ((float*)&e)[h & 3] = -INFINITY;
        } else {
            for (int c = 0; c < 16; c++) {
                float qq = qs[c*64 + w];
                float4 kv = ((const float4*)ks)[c*16 + (j4 - 16)];
                e.x += qq * kv.x; e.y += qq * kv.y; e.z += qq * kv.z; e.w += qq * kv.w;
            }
        }
        ((float4*)E)[w*32 + j4] = e;
    }
    __syncthreads();

    const int lane = t & 31, wid = t >> 5;
    for (int r = 0; r < 8; r++) {
        const int w = wid*8 + r;
        float v0 = E[w*128 + lane],      v1 = E[w*128 + lane + 32];
        float v2 = E[w*128 + lane + 64], v3 = E[w*128 + lane + 96];
        float m = fmaxf(fmaxf(v0, v1), fmaxf(v2, v3));
        #pragma unroll
        for (int s = 16; s; s >>= 1) m = fmaxf(m, __shfl_xor_sync(0xffffffffu, m, s));
        float e0 = expf(v0 - m), e1 = expf(v1 - m), e2 = expf(v2 - m), e3 = expf(v3 - m);
        float sum = e0 + e1 + e2 + e3;
        #pragma unroll
        for (int s = 16; s; s >>= 1) sum += __shfl_xor_sync(0xffffffffu, sum, s);
        float inv = 1.f / sum;
        float* dst = att + (size_t)((b*HH + h)*WW + w)*128;
        dst[lane] = e0*inv; dst[lane+32] = e1*inv; dst[lane+64] = e2*inv; dst[lane+96] = e3*inv;
    }
}

__global__ void __launch_bounds__(256) oH_k(
    const float* __restrict__ att, const float* __restrict__ vt,
    float* __restrict__ outb)
{
    extern __shared__ __align__(16) float sm[];
    float* As = sm;
    float* Vs = sm + 64*68;

    const int t = threadIdx.x;
    const int w = blockIdx.x, b = blockIdx.y;

    for (int idx = t; idx < 4096; idx += 256) {
        int hh = idx >> 6, g = idx & 63;
        As[g*68 + hh] = att[(size_t)((b*HH + hh)*WW + w)*128 + g];
    }
    for (int idx = t; idx < 8192; idx += 256) {
        int c = idx >> 6, g = idx & 63;
        Vs[g*132 + c] = vt[((b*CI + c)*WW + w)*HH + g];
    }
    __syncthreads();

    const int c0 = (t & 31) * 4;
    const int h0 = (t >> 5) * 8;
    float acc[8][4];
    #pragma unroll
    for (int i = 0; i < 8; i++)
        #pragma unroll
        for (int j = 0; j < 4; j++) acc[i][j] = 0.f;

    for (int g = 0; g < 64; g++) {
        float4 v4 = *(const float4*)&Vs[g*132 + c0];
        #pragma unroll
        for (int hi = 0; hi < 8; hi++) {
            float av = As[g*68 + h0 + hi];
            acc[hi][0] += av * v4.x; acc[hi][1] += av * v4.y;
            acc[hi][2] += av * v4.z; acc[hi][3] += av * v4.w;
        }
    }
    #pragma unroll
    for (int hi = 0; hi < 8; hi++)
        #pragma unroll
        for (int ci = 0; ci < 4; ci++)
            outb[((b*CI + c0 + ci)*HH + h0 + hi)*WW + w] = acc[hi][ci];
}

__global__ void __launch_bounds__(256) oW_k(
    const float* __restrict__ att, const float* __restrict__ v,
    const float* __restrict__ feat, const float* __restrict__ gamma,
    float* __restrict__ outb)
{
    extern __shared__ __align__(16) float sm[];
    float* Aw = sm;
    float* Ws = sm + 64*68;

    const int t = threadIdx.x;
    const int h = blockIdx.x, b = blockIdx.y;

    for (int idx = t; idx < 4096; idx += 256) {
        int w = idx >> 6, wp = idx & 63;
        Aw[wp*68 + w] = att[(size_t)((b*HH + h)*WW + w)*128 + 64 + wp];
    }
    for (int idx = t; idx < 8192; idx += 256) {
        int c = idx >> 6, wp = idx & 63;
        Ws[wp*132 + c] = v[((b*CI + c)*HH + h)*WW + wp];
    }
    __syncthreads();

    const int c0 = (t & 31) * 4;
    const int w0 = (t >> 5) * 8;
    float acc[8][4];
    #pragma unroll
    for (int i = 0; i < 8; i++)
        #pragma unroll
        for (int j = 0; j < 4; j++) acc[i][j] = 0.f;

    for (int wp = 0; wp < 64; wp++) {
        float4 v4 = *(const float4*)&Ws[wp*132 + c0];
        #pragma unroll
        for (int wi = 0; wi < 8; wi++) {
            float av = Aw[wp*68 + w0 + wi];
            acc[wi][0] += av * v4.x; acc[wi][1] += av * v4.y;
            acc[wi][2] += av * v4.z; acc[wi][3] += av * v4.w;
        }
    }

    const float g = gamma[0];
    #pragma unroll
    for (int ci = 0; ci < 4; ci++) {
        const int base = ((b*CI + c0 + ci)*HH + h)*WW + w0;
        float4 f0 = *(const float4*)&feat[base];
        float4 f1 = *(const float4*)&feat[base + 4];
        float4 o0 = *(const float4*)&outb[base];
        float4 o1 = *(const float4*)&outb[base + 4];
        float4 r0 = make_float4(f0.x + g*(o0.x + acc[0][ci]),
                                f0.y + g*(o0.y + acc[1][ci]),
                                f0.z + g*(o0.z + acc[2][ci]),
                                f0.w + g*(o0.w + acc[3][ci]));
        float4 r1 = make_float4(f1.x + g*(o1.x + acc[4][ci]),
                                f1.y + g*(o1.y + acc[5][ci]),
                                f1.z + g*(o1.z + acc[6][ci]),
                                f1.w + g*(o1.w + acc[7][ci]));
        *(float4*)&outb[base]     = r0;
        *(float4*)&outb[base + 4] = r1;
    }
}

// =====================================================================
extern "C" void kernel_launch(void* const* d_in, const int* in_sizes, int n_in,
                              void* d_out, int out_size)
{
    (void)in_sizes; (void)n_in; (void)out_size;
    const float* x       = (const float*)d_in[0];
    const float* conva_w = (const float*)d_in[1];
    const float* bn1_g   = (const float*)d_in[2];
    const float* bn1_b   = (const float*)d_in[3];
    const float* bn1_m   = (const float*)d_in[4];
    const float* bn1_v   = (const float*)d_in[5];
    const float* wq      = (const float*)d_in[6];
    const float* bq      = (const float*)d_in[7];
    const float* wk      = (const float*)d_in[8];
    const float* bk      = (const float*)d_in[9];
    const float* wv      = (const float*)d_in[10];
    const float* bv      = (const float*)d_in[11];
    const float* gamma   = (const float*)d_in[12];
    const float* convb_w = (const float*)d_in[13];
    const float* bn2_g   = (const float*)d_in[14];
    const float* bn2_b   = (const float*)d_in[15];
    const float* bn2_m   = (const float*)d_in[16];
    const float* bn2_v   = (const float*)d_in[17];
    const float* bott_w  = (const float*)d_in[18];
    float* out = (float*)d_out;

    float *featA, *featB, *qb, *kb, *ktb, *vb, *vtb, *attb;
    cudaGetSymbolAddress((void**)&featA, g_featA);
    cudaGetSymbolAddress((void**)&featB, g_featB);
    cudaGetSymbolAddress((void**)&qb,    g_q);
    cudaGetSymbolAddress((void**)&kb,    g_k);
    cudaGetSymbolAddress((void**)&ktb,   g_kt);
    cudaGetSymbolAddress((void**)&vb,    g_v);
    cudaGetSymbolAddress((void**)&vtb,   g_vt);
    cudaGetSymbolAddress((void**)&attb,  g_att);

    __half *xph, *xpl, *x2h, *x2l, *whi;
    cudaGetSymbolAddress((void**)&xph, g_xph4);
    cudaGetSymbolAddress((void**)&xpl, g_xpl4);
    cudaGetSymbolAddress((void**)&x2h, g_x2h4);
    cudaGetSymbolAddress((void**)&x2l, g_x2l4);
    cudaGetSymbolAddress((void**)&whi, g_whi4);

    const int QKV_SMEM = (128*128 + 128*164) * 4;
    const int OHW_SMEM = (64*68 + 64*132) * 4;
    cudaFuncSetAttribute(qkv_k,     cudaFuncAttributeMaxDynamicSharedMemorySize, QKV_SMEM);
    cudaFuncSetAttribute(oH_k,      cudaFuncAttributeMaxDynamicSharedMemorySize, OHW_SMEM);
    cudaFuncSetAttribute(oW_k,      cudaFuncAttributeMaxDynamicSharedMemorySize, OHW_SMEM);
    cudaFuncSetAttribute(convmma_k, cudaFuncAttributeMaxDynamicSharedMemorySize, SM_TOTAL);

    // ---- conv1 (512 -> 128) + BN1 ----
    wprep_k<<<512, 256>>>(conva_w, CI, CIN, whi);
    pad_k<<<dim3(64, CIN/64, BB), 256>>>(x, CIN, xph, xpl, 640, 0);
    zero_border_k<<<1024, 256>>>(xph, xpl, 640);
    convmma_k<<<dim3(32, BB), 256, SM_TOTAL>>>(xph, xpl, 640, CIN/64,
                                               whi, CIN, CI,
                                               bn1_g, bn1_b, bn1_m, bn1_v,
                                               featA, 0);

    // ---- criss-cross attention x2 ----
    float* F = featA;
    float* G = featB;
    for (int it = 0; it < 2; it++) {
        qkv_k<<<dim3(32, BB), 256, QKV_SMEM>>>(F, wq, bq, wk, bk, wv, bv, qb, kb, vb);
        trans_k<<<BB*CQ, 256>>>(kb, ktb);
        trans_k<<<BB*CI, 256>>>(vb, vtb);
        att_k<<<dim3(HH, BB), 256>>>(qb, kb, ktb, attb);
        oH_k<<<dim3(WW, BB), 256, OHW_SMEM>>>(attb, vtb, G);
        oW_k<<<dim3(HH, BB), 256, OHW_SMEM>>>(attb, vb, F, gamma, G);
        float* tmp = F; F = G; G = tmp;
    }
    // after 2 iters: F = featA, G = featB

    // ---- convb (128 -> 128) + BN2 ----
    wprep_k<<<576, 256>>>(convb_w, CI, CI, whi);
    pad_k<<<dim3(64, CI/64, BB), 256>>>(F, CI, x2h, x2l, 128, 0);
    zero_border_k<<<1024, 256>>>(x2h, x2l, 128);
    convmma_k<<<dim3(32, BB), 256, SM_TOTAL>>>(x2h, x2l, 128, CI/64,
                                               whi, CI, CI,
                                               bn2_g, bn2_b, bn2_m, bn2_v,
                                               G, 0);

    // ---- bottleneck conv (concat 512+128 -> 512) + ELU ----
    pad_k<<<dim3(64, CI/64, BB), 256>>>(G, CI, xph, xpl, 640, CIN);
    wprep_k<<<4096, 256>>>(bott_w, CIN, CIN + CI, whi);
    convmma_k<<<dim3(32, BB*(CIN/128)), 256, SM_TOTAL>>>(xph, xpl, 640, (CIN + CI)/64,
                                                         whi, CIN + CI, CIN,
                                                         nullptr, nullptr, nullptr, nullptr,
                                                         out, 1);
}

// round 5
// speedup vs baseline: 9.6177x; 1.2352x over previous
#include <cuda_runtime.h>
#include <cuda_fp16.h>
#include <math.h>
#include <stdint.h>

#define BB 8
#define HH 64
#define WW 64
#define HWSZ 4096
#define CI 128
#define CQ 16
#define CIN 512

// ---------------- scratch buffers (static device allocations) ----------------
__device__ float g_featA[BB*CI*HWSZ];
__device__ float g_featB[BB*CI*HWSZ];
__device__ float g_q [BB*CQ*HWSZ];
__device__ float g_k [BB*CQ*HWSZ];
__device__ float g_kt[BB*CQ*HWSZ];
__device__ float g_v [BB*CI*HWSZ];
__device__ float g_vt[BB*CI*HWSZ];
__device__ float g_att[BB*HH*WW*128];

// padded NHWC fp16 hi/lo feature maps (16B aligned via uint4)
#define XP640_ELEMS (8ULL*66*66*640)
#define XP128_ELEMS (8ULL*66*66*128)
#define WSP_ELEMS   (9ULL*512*640)
__device__ uint4 g_xph4[XP640_ELEMS/8];
__device__ uint4 g_xpl4[XP640_ELEMS/8];
__device__ uint4 g_x2h4[XP128_ELEMS/8];
__device__ uint4 g_x2l4[XP128_ELEMS/8];
__device__ uint4 g_whi4[WSP_ELEMS/8];

// =====================================================================
// PTX helpers (compute_103-safe: mma.sync / ldmatrix / cp.async only)
// =====================================================================
__device__ __forceinline__ uint32_t smem_u32(const void* p) {
    uint32_t a;
    asm("{ .reg .u64 t; cvta.to.shared.u64 t, %1; cvt.u32.u64 %0, t; }" : "=r"(a) : "l"(p));
    return a;
}
__device__ __forceinline__ void cpa16(uint32_t dst, const void* src) {
    asm volatile("cp.async.cg.shared.global [%0], [%1], 16;" :: "r"(dst), "l"(src) : "memory");
}
__device__ __forceinline__ void cpa_commit() {
    asm volatile("cp.async.commit_group;" ::: "memory");
}
__device__ __forceinline__ void cpa_wait0() {
    asm volatile("cp.async.wait_group 0;" ::: "memory");
}
__device__ __forceinline__ void ldsm4(uint32_t* r, uint32_t addr) {
    asm volatile("ldmatrix.sync.aligned.m8n8.x4.shared.b16 {%0,%1,%2,%3}, [%4];"
                 : "=r"(r[0]), "=r"(r[1]), "=r"(r[2]), "=r"(r[3]) : "r"(addr));
}
__device__ __forceinline__ void mma16816(float* c, const uint32_t* a, const uint32_t* b) {
    asm volatile(
        "mma.sync.aligned.m16n8k16.row.col.f32.f16.f16.f32 "
        "{%0,%1,%2,%3}, {%4,%5,%6,%7}, {%8,%9}, {%0,%1,%2,%3};"
        : "+f"(c[0]), "+f"(c[1]), "+f"(c[2]), "+f"(c[3])
        : "r"(a[0]), "r"(a[1]), "r"(a[2]), "r"(a[3]), "r"(b[0]), "r"(b[1]));
}
__device__ __forceinline__ uint32_t sw128(uint32_t off) {
    return off ^ ((off >> 3) & 0x70);
}

// =====================================================================
// prep: NCHW fp32 -> padded NHWC fp16 hi/lo (interior only)
// =====================================================================
__global__ void __launch_bounds__(256) pad_k(
    const float* __restrict__ src, int C,
    __half* __restrict__ dh, __half* __restrict__ dl,
    int pitch, int colofs)
{
    __shared__ float s[64][65];
    const int y = blockIdx.x, cbase = blockIdx.y * 64, b = blockIdx.z;
    const int t = threadIdx.x;
    for (int idx = t; idx < 4096; idx += 256) {
        int icl = idx >> 6, x = idx & 63;
        s[icl][x] = src[((size_t)(b*C + cbase + icl)*64 + y)*64 + x];
    }
    __syncthreads();
    for (int idx = t; idx < 4096; idx += 256) {
        int x = idx >> 6, icl = idx & 63;
        float v = s[icl][x];
        __half h = __float2half_rn(v);
        __half l = __float2half_rn(v - __half2float(h));
        size_t o = ((size_t)(b*66 + y + 1)*66 + (x + 1))*pitch + colofs + cbase + icl;
        dh[o] = h; dl[o] = l;
    }
}

__global__ void __launch_bounds__(256) zero_border_k(
    __half* __restrict__ dh, __half* __restrict__ dl, int pitch)
{
    const int total = 8 * 260 * pitch;
    for (int idx = blockIdx.x*256 + threadIdx.x; idx < total; idx += gridDim.x*256) {
        int ic = idx % pitch;
        int r  = idx / pitch;
        int b  = r / 260;
        int pos = r % 260;
        int yy, xx;
        if      (pos < 66)  { yy = 0;  xx = pos; }
        else if (pos < 132) { yy = 65; xx = pos - 66; }
        else if (pos < 196) { yy = pos - 132 + 1; xx = 0; }
        else                { yy = pos - 196 + 1; xx = 65; }
        size_t o = ((size_t)(b*66 + yy)*66 + xx)*pitch + ic;
        dh[o] = __float2half_rn(0.f);
        dl[o] = __float2half_rn(0.f);
    }
}

// weights: w[oc][ic][3][3] fp32 -> Wh [tap][oc][ic] fp16 (single)
__global__ void __launch_bounds__(256) wprep_k(
    const float* __restrict__ w, int Cout, int Ctot,
    __half* __restrict__ wh)
{
    const int total = Cout * Ctot * 9;
    for (int idx = blockIdx.x*256 + threadIdx.x; idx < total; idx += gridDim.x*256) {
        int ic  = idx % Ctot;
        int r   = idx / Ctot;
        int oc  = r % Cout;
        int tap = r / Cout;
        float v = w[(size_t)(oc*Ctot + ic)*9 + tap];
        wh[(size_t)(tap*Cout + oc)*Ctot + ic] = __float2half_rn(v);
    }
}

// =====================================================================
// HMMA implicit-GEMM conv3x3: CTA tile M=128 oc x N=128 px (2 rows),
// warp tile 64x32, K-chunk = (tap, 64 ic).
// fp16: W single, X hi/lo split -> 2 MMAs per fragment pair.
// 128B pitch + sw128 swizzle (conflict-free, tighter smem),
// cp.async double-buffered, launch_bounds(256,2) -> 2 CTAs/SM.
// Epilogue: mode 0 = BN, mode 1 = ELU(512).
// =====================================================================
#define TILE_B (128*128)      // 16384 B per tile (128 rows x 128B)
#define OFF_A  0
#define OFF_BH TILE_B
#define OFF_BL (2*TILE_B)
#define BUF_B  (3*TILE_B)     // 49152 B per buffer
#define SM_TOTAL (2*BUF_B)    // 98304 B

__global__ void __launch_bounds__(256, 2) convmma_k(
    const __half* __restrict__ Xh, const __half* __restrict__ Xl,
    int pitch, int chunks,
    const __half* __restrict__ Wh,
    int Ctot, int Cout,
    const float* __restrict__ bn_g, const float* __restrict__ bn_b,
    const float* __restrict__ bn_m, const float* __restrict__ bn_v,
    float* __restrict__ out, int mode)
{
    extern __shared__ __align__(128) char smem[];
    const uint32_t sb = smem_u32(smem);
    const int t = threadIdx.x;
    const int warp = t >> 5, lane = t & 31;
    const int nog = Cout >> 7;
    const int ocg = blockIdx.y % nog;
    const int b   = blockIdx.y / nog;
    const int y0  = blockIdx.x * 2;
    const int ocb = ocg * 128;

    const int q8 = t & 7;     // 16B sector (8 fp16)
    const int r0 = t >> 3;    // base row 0..31

    const int T = chunks * 9;

    // ---- async tile loader: tile idx i -> (chunk, tap) ----
    auto issue_tile = [&](int i) {
        const int c   = i / 9;
        const int tap = i - c*9;
        const int dy  = tap / 3, dx = tap - dy*3;
        const int ic0 = c * 64;
        const uint32_t base = sb + (uint32_t)(i & 1) * BUF_B;
        #pragma unroll
        for (int p = 0; p < 4; p++) {
            const int m = r0 + 32*p;
            const uint32_t so = sw128((uint32_t)(m*128 + q8*16));
            const size_t ga = (size_t)(tap*Cout + ocb + m)*Ctot + ic0 + q8*8;
            cpa16(base + OFF_A + so, Wh + ga);
            const int yl = m >> 6, x = m & 63;
            const size_t gb = ((size_t)(b*66 + y0 + yl + dy)*66 + (x + dx))*pitch
                              + ic0 + q8*8;
            cpa16(base + OFF_BH + so, Xh + gb);
            cpa16(base + OFF_BL + so, Xl + gb);
        }
        cpa_commit();
    };

    // ---- accumulators ----
    const int m0 = (warp >> 2) * 64;
    const int n0 = (warp & 3) * 32;
    float acc[4][4][4];
    #pragma unroll
    for (int mi = 0; mi < 4; mi++)
        #pragma unroll
        for (int nj = 0; nj < 4; nj++)
            #pragma unroll
            for (int u = 0; u < 4; u++) acc[mi][nj][u] = 0.f;

    const int arow  = lane & 15;
    const int acolb = ((lane >> 4) << 3) * 2;           // + k0 bytes later
    const int brow  = (lane & 7) + ((lane >> 4) << 3);
    const int bcolb = (((lane >> 3) & 1) << 3) * 2;     // + k0 bytes later

    issue_tile(0);

    for (int i = 0; i < T; i++) {
        cpa_wait0();           // tile i resident (only group i outstanding)
        __syncthreads();       // all warps done with compute(i-1) -> buffer (i+1)&1 free
        if (i + 1 < T) issue_tile(i + 1);   // overlaps compute below

        const uint32_t base = sb + (uint32_t)(i & 1) * BUF_B;
        const uint32_t sA  = base + OFF_A;
        const uint32_t sBH = base + OFF_BH, sBL = base + OFF_BL;

        #pragma unroll
        for (int kk = 0; kk < 4; kk++) {
            const int k0b = kk * 32;   // 16 fp16 = 32 bytes
            uint32_t a[4][4], bh[2][4], bl[2][4];
            #pragma unroll
            for (int mi = 0; mi < 4; mi++) {
                const uint32_t ro = sw128((uint32_t)((m0 + mi*16 + arow) * 128 + k0b + acolb));
                ldsm4(a[mi], sA + ro);
            }
            #pragma unroll
            for (int ni = 0; ni < 2; ni++) {
                const uint32_t ro = sw128((uint32_t)((n0 + ni*16 + brow) * 128 + k0b + bcolb));
                ldsm4(bh[ni], sBH + ro);
                ldsm4(bl[ni], sBL + ro);
            }
            #pragma unroll
            for (int mi = 0; mi < 4; mi++)
                #pragma unroll
                for (int nj = 0; nj < 4; nj++) {
                    const uint32_t* bhp = &bh[nj >> 1][(nj & 1) * 2];
                    const uint32_t* blp = &bl[nj >> 1][(nj & 1) * 2];
                    mma16816(acc[mi][nj], a[mi], bhp);
                    mma16816(acc[mi][nj], a[mi], blp);
                }
        }
    }

    // ---- epilogue ----
    const int g  = lane >> 2;
    const int t2 = (lane & 3) * 2;
    #pragma unroll
    for (int mi = 0; mi < 4; mi++) {
        const int ocA = ocb + m0 + mi*16 + g;
        const int ocB = ocA + 8;
        float scA = 1.f, biA = 0.f, scB = 1.f, biB = 0.f;
        if (mode == 0) {
            scA = bn_g[ocA] * rsqrtf(bn_v[ocA] + 1e-5f);
            biA = bn_b[ocA] - bn_m[ocA] * scA;
            scB = bn_g[ocB] * rsqrtf(bn_v[ocB] + 1e-5f);
            biB = bn_b[ocB] - bn_m[ocB] * scB;
        }
        #pragma unroll
        for (int nj = 0; nj < 4; nj++) {
            const int n  = n0 + nj*8 + t2;
            const int yl = n >> 6, x = n & 63;
            float v0 = acc[mi][nj][0], v1 = acc[mi][nj][1];
            float v2 = acc[mi][nj][2], v3 = acc[mi][nj][3];
            if (mode == 0) {
                v0 = v0*scA + biA; v1 = v1*scA + biA;
                v2 = v2*scB + biB; v3 = v3*scB + biB;
            } else {
                if (v0 <= 0.f) v0 = 512.0f * expm1f(v0);
                if (v1 <= 0.f) v1 = 512.0f * expm1f(v1);
                if (v2 <= 0.f) v2 = 512.0f * expm1f(v2);
                if (v3 <= 0.f) v3 = 512.0f * expm1f(v3);
            }
            *(float2*)&out[((size_t)(b*Cout + ocA)*64 + y0 + yl)*64 + x] = make_float2(v0, v1);
            *(float2*)&out[((size_t)(b*Cout + ocB)*64 + y0 + yl)*64 + x] = make_float2(v2, v3);
        }
    }
}

// =====================================================================
// attention kernels (fp32 path)
// =====================================================================
__global__ void __launch_bounds__(256) qkv_k(
    const float* __restrict__ feat,
    const float* __restrict__ wq, const float* __restrict__ bq,
    const float* __restrict__ wk, const float* __restrict__ bk,
    const float* __restrict__ wv, const float* __restrict__ bv,
    float* __restrict__ q, float* __restrict__ k, float* __restrict__ v)
{
    extern __shared__ __align__(16) float sm[];
    float* s_in = sm;               // [128 ic][128 px]
    float* s_w  = sm + 128*128;     // [128 ic][pitch 164]

    const int t   = threadIdx.x;
    const int pxb = blockIdx.x * 128;
    const int b   = blockIdx.y;

    const float4* f4 = (const float4*)(feat + (size_t)b*CI*HWSZ);
    for (int idx = t; idx < 128*32; idx += 256) {
        int ic = idx >> 5, p4 = idx & 31;
        ((float4*)s_in)[ic*32 + p4] = f4[ic*(HWSZ/4) + (pxb >> 2) + p4];
    }
    for (int idx = t; idx < 16*128;  idx += 256) { int oc = idx >> 7, ic = idx & 127; s_w[ic*164 + oc]       = wq[idx]; }
    for (int idx = t; idx < 16*128;  idx += 256) { int oc = idx >> 7, ic = idx & 127; s_w[ic*164 + 16 + oc]  = wk[idx]; }
    for (int idx = t; idx < 128*128; idx += 256) { int oc = idx >> 7, ic = idx & 127; s_w[ic*164 + 32 + oc]  = wv[idx]; }
    __syncthreads();

    const int l   = t & 31;
    const int oc0 = (t >> 5) * 20;

    float acc[20][4];
    #pragma unroll
    for (int j = 0; j < 20; j++)
        #pragma unroll
        for (int i = 0; i < 4; i++) acc[j][i] = 0.f;

    for (int ic = 0; ic < 128; ic++) {
        float4 x4 = ((const float4*)s_in)[ic*32 + l];
        const float* wr = s_w + ic*164 + oc0;
        #pragma unroll
        for (int j = 0; j < 5; j++) {
            float4 w4 = *(const float4*)(wr + 4*j);
            acc[4*j+0][0] += w4.x * x4.x; acc[4*j+0][1] += w4.x * x4.y;
            acc[4*j+0][2] += w4.x * x4.z; acc[4*j+0][3] += w4.x * x4.w;
            acc[4*j+1][0] += w4.y * x4.x; acc[4*j+1][1] += w4.y * x4.y;
            acc[4*j+1][2] += w4.y * x4.z; acc[4*j+1][3] += w4.y * x4.w;
            acc[4*j+2][0] += w4.z * x4.x; acc[4*j+2][1] += w4.z * x4.y;
            acc[4*j+2][2] += w4.z * x4.z; acc[4*j+2][3] += w4.z * x4.w;
            acc[4*j+3][0] += w4.w * x4.x; acc[4*j+3][1] += w4.w * x4.y;
            acc[4*j+3][2] += w4.w * x4.z; acc[4*j+3][3] += w4.w * x4.w;
        }
    }

    #pragma unroll
    for (int j = 0; j < 20; j++) {
        const int oc = oc0 + j;
        float bias; float* dst; int o; int C;
        if (oc < 16)      { bias = bq[oc];      dst = q; o = oc;      C = CQ; }
        else if (oc < 32) { bias = bk[oc - 16]; dst = k; o = oc - 16; C = CQ; }
        else              { bias = bv[oc - 32]; dst = v; o = oc - 32; C = CI; }
        *(float4*)&dst[((size_t)b*C + o)*HWSZ + pxb + l*4] =
            make_float4(acc[j][0] + bias, acc[j][1] + bias,
                        acc[j][2] + bias, acc[j][3] + bias);
    }
}

__global__ void __launch_bounds__(256) trans_k(const float* __restrict__ in,
                                               float* __restrict__ out)
{
    __shared__ float s[64][65];
    const float* src = in  + (size_t)blockIdx.x * 4096;
    float*       dst = out + (size_t)blockIdx.x * 4096;
    for (int idx = threadIdx.x; idx < 4096; idx += 256)
        s[idx >> 6][idx & 63] = src[idx];
    __syncthreads();
    for (int idx = threadIdx.x; idx < 4096; idx += 256)
        dst[idx] = s[idx & 63][idx >> 6];
}

__global__ void __launch_bounds__(256) att_k(
    const float* __restrict__ q, const float* __restrict__ k,
    const float* __restrict__ kt, float* __restrict__ att)
{
    __shared__ float qs[16*64];
    __shared__ float ks[16*64];
    __shared__ float E[64*128];

    const int t = threadIdx.x;
    const int h = blockIdx.x, b = blockIdx.y;

    for (int idx = t; idx < 1024; idx += 256) {
        int c = idx >> 6, w = idx & 63;
        qs[idx] = q[((b*CQ + c)*HH + h)*WW + w];
        ks[idx] = k[((b*CQ + c)*HH + h)*WW + w];
    }
    __syncthreads();

    for (int idx = t; idx < 2048; idx += 256) {
        const int w  = idx >> 5;
        const int j4 = idx & 31;
        float4 e = make_float4(0.f, 0.f, 0.f, 0.f);
        if (j4 < 16) {
            for (int c = 0; c < 16; c++) {
                float qq = qs[c*64 + w];
                float4 kv = ((const float4*)kt)[((b*CQ + c)*WW + w)*16 + j4];
                e.x += qq * kv.x; e.y += qq * kv.y; e.z += qq * kv.z; e.w += qq * kv.w;
            }
            if ((h >> 2) == j4) ((float*)&e)[h & 3] = -INFINITY;
        } else {
            for (int c = 0; c < 16; c++) {
                float qq = qs[c*64 + w];
                float4 kv = ((const float4*)ks)[c*16 + (j4 - 16)];
                e.x += qq * kv.x; e.y += qq * kv.y; e.z += qq * kv.z; e.w += qq * kv.w;
            }
        }
        ((float4*)E)[w*32 + j4] = e;
    }
    __syncthreads();

    const int lane = t & 31, wid = t >> 5;
    for (int r = 0; r < 8; r++) {
        const int w = wid*8 + r;
        float v0 = E[w*128 + lane],      v1 = E[w*128 + lane + 32];
        float v2 = E[w*128 + lane + 64], v3 = E[w*128 + lane + 96];
        float m = fmaxf(fmaxf(v0, v1), fmaxf(v2, v3));
        #pragma unroll
        for (int s = 16; s; s >>= 1) m = fmaxf(m, __shfl_xor_sync(0xffffffffu, m, s));
        float e0 = expf(v0 - m), e1 = expf(v1 - m), e2 = expf(v2 - m), e3 = expf(v3 - m);
        float sum = e0 + e1 + e2 + e3;
        #pragma unroll
        for (int s = 16; s; s >>= 1) sum += __shfl_xor_sync(0xffffffffu, sum, s);
        float inv = 1.f / sum;
        float* dst = att + (size_t)((b*HH + h)*WW + w)*128;
        dst[lane] = e0*inv; dst[lane+32] = e1*inv; dst[lane+64] = e2*inv; dst[lane+96] = e3*inv;
    }
}

__global__ void __launch_bounds__(256) oH_k(
    const float* __restrict__ att, const float* __restrict__ vt,
    float* __restrict__ outb)
{
    extern __shared__ __align__(16) float sm[];
    float* As = sm;
    float* Vs = sm + 64*68;

    const int t = threadIdx.x;
    const int w = blockIdx.x, b = blockIdx.y;

    for (int idx = t; idx < 4096; idx += 256) {
        int hh = idx >> 6, g = idx & 63;
        As[g*68 + hh] = att[(size_t)((b*HH + hh)*WW + w)*128 + g];
    }
    for (int idx = t; idx < 8192; idx += 256) {
        int c = idx >> 6, g = idx & 63;
        Vs[g*132 + c] = vt[((b*CI + c)*WW + w)*HH + g];
    }
    __syncthreads();

    const int c0 = (t & 31) * 4;
    const int h0 = (t >> 5) * 8;
    float acc[8][4];
    #pragma unroll
    for (int i = 0; i < 8; i++)
        #pragma unroll
        for (int j = 0; j < 4; j++) acc[i][j] = 0.f;

    for (int g = 0; g < 64; g++) {
        float4 v4 = *(const float4*)&Vs[g*132 + c0];
        #pragma unroll
        for (int hi = 0; hi < 8; hi++) {
            float av = As[g*68 + h0 + hi];
            acc[hi][0] += av * v4.x; acc[hi][1] += av * v4.y;
            acc[hi][2] += av * v4.z; acc[hi][3] += av * v4.w;
        }
    }
    #pragma unroll
    for (int hi = 0; hi < 8; hi++)
        #pragma unroll
        for (int ci = 0; ci < 4; ci++)
            outb[((b*CI + c0 + ci)*HH + h0 + hi)*WW + w] = acc[hi][ci];
}

__global__ void __launch_bounds__(256) oW_k(
    const float* __restrict__ att, const float* __restrict__ v,
    const float* __restrict__ feat, const float* __restrict__ gamma,
    float* __restrict__ outb)
{
    extern __shared__ __align__(16) float sm[];
    float* Aw = sm;
    float* Ws = sm + 64*68;

    const int t = threadIdx.x;
    const int h = blockIdx.x, b = blockIdx.y;

    for (int idx = t; idx < 4096; idx += 256) {
        int w = idx >> 6, wp = idx & 63;
        Aw[wp*68 + w] = att[(size_t)((b*HH + h)*WW + w)*128 + 64 + wp];
    }
    for (int idx = t; idx < 8192; idx += 256) {
        int c = idx >> 6, wp = idx & 63;
        Ws[wp*132 + c] = v[((b*CI + c)*HH + h)*WW + wp];
    }
    __syncthreads();

    const int c0 = (t & 31) * 4;
    const int w0 = (t >> 5) * 8;
    float acc[8][4];
    #pragma unroll
    for (int i = 0; i < 8; i++)
        #pragma unroll
        for (int j = 0; j < 4; j++) acc[i][j] = 0.f;

    for (int wp = 0; wp < 64; wp++) {
        float4 v4 = *(const float4*)&Ws[wp*132 + c0];
        #pragma unroll
        for (int wi = 0; wi < 8; wi++) {
            float av = Aw[wp*68 + w0 + wi];
            acc[wi][0] += av * v4.x; acc[wi][1] += av * v4.y;
            acc[wi][2] += av * v4.z; acc[wi][3] += av * v4.w;
        }
    }

    const float g = gamma[0];
    #pragma unroll
    for (int ci = 0; ci < 4; ci++) {
        const int base = ((b*CI + c0 + ci)*HH + h)*WW + w0;
        float4 f0 = *(const float4*)&feat[base];
        float4 f1 = *(const float4*)&feat[base + 4];
        float4 o0 = *(const float4*)&outb[base];
        float4 o1 = *(const float4*)&outb[base + 4];
        float4 r0 = make_float4(f0.x + g*(o0.x + acc[0][ci]),
                                f0.y + g*(o0.y + acc[1][ci]),
                                f0.z + g*(o0.z + acc[2][ci]),
                                f0.w + g*(o0.w + acc[3][ci]));
        float4 r1 = make_float4(f1.x + g*(o1.x + acc[4][ci]),
                                f1.y + g*(o1.y + acc[5][ci]),
                                f1.z + g*(o1.z + acc[6][ci]),
                                f1.w + g*(o1.w + acc[7][ci]));
        *(float4*)&outb[base]     = r0;
        *(float4*)&outb[base + 4] = r1;
    }
}

// =====================================================================
extern "C" void kernel_launch(void* const* d_in, const int* in_sizes, int n_in,
                              void* d_out, int out_size)
{
    (void)in_sizes; (void)n_in; (void)out_size;
    const float* x       = (const float*)d_in[0];
    const float* conva_w = (const float*)d_in[1];
    const float* bn1_g   = (const float*)d_in[2];
    const float* bn1_b   = (const float*)d_in[3];
    const float* bn1_m   = (const float*)d_in[4];
    const float* bn1_v   = (const float*)d_in[5];
    const float* wq      = (const float*)d_in[6];
    const float* bq      = (const float*)d_in[7];
    const float* wk      = (const float*)d_in[8];
    const float* bk      = (const float*)d_in[9];
    const float* wv      = (const float*)d_in[10];
    const float* bv      = (const float*)d_in[11];
    const float* gamma   = (const float*)d_in[12];
    const float* convb_w = (const float*)d_in[13];
    const float* bn2_g   = (const float*)d_in[14];
    const float* bn2_b   = (const float*)d_in[15];
    const float* bn2_m   = (const float*)d_in[16];
    const float* bn2_v   = (const float*)d_in[17];
    const float* bott_w  = (const float*)d_in[18];
    float* out = (float*)d_out;

    float *featA, *featB, *qb, *kb, *ktb, *vb, *vtb, *attb;
    cudaGetSymbolAddress((void**)&featA, g_featA);
    cudaGetSymbolAddress((void**)&featB, g_featB);
    cudaGetSymbolAddress((void**)&qb,    g_q);
    cudaGetSymbolAddress((void**)&kb,    g_k);
    cudaGetSymbolAddress((void**)&ktb,   g_kt);
    cudaGetSymbolAddress((void**)&vb,    g_v);
    cudaGetSymbolAddress((void**)&vtb,   g_vt);
    cudaGetSymbolAddress((void**)&attb,  g_att);

    __half *xph, *xpl, *x2h, *x2l, *whi;
    cudaGetSymbolAddress((void**)&xph, g_xph4);
    cudaGetSymbolAddress((void**)&xpl, g_xpl4);
    cudaGetSymbolAddress((void**)&x2h, g_x2h4);
    cudaGetSymbolAddress((void**)&x2l, g_x2l4);
    cudaGetSymbolAddress((void**)&whi, g_whi4);

    const int QKV_SMEM = (128*128 + 128*164) * 4;
    const int OHW_SMEM = (64*68 + 64*132) * 4;
    cudaFuncSetAttribute(qkv_k,     cudaFuncAttributeMaxDynamicSharedMemorySize, QKV_SMEM);
    cudaFuncSetAttribute(oH_k,      cudaFuncAttributeMaxDynamicSharedMemorySize, OHW_SMEM);
    cudaFuncSetAttribute(oW_k,      cudaFuncAttributeMaxDynamicSharedMemorySize, OHW_SMEM);
    cudaFuncSetAttribute(convmma_k, cudaFuncAttributeMaxDynamicSharedMemorySize, SM_TOTAL);

    // ---- conv1 (512 -> 128) + BN1 ----
    wprep_k<<<512, 256>>>(conva_w, CI, CIN, whi);
    pad_k<<<dim3(64, CIN/64, BB), 256>>>(x, CIN, xph, xpl, 640, 0);
    zero_border_k<<<1024, 256>>>(xph, xpl, 640);
    convmma_k<<<dim3(32, BB), 256, SM_TOTAL>>>(xph, xpl, 640, CIN/64,
                                               whi, CIN, CI,
                                               bn1_g, bn1_b, bn1_m, bn1_v,
                                               featA, 0);

    // ---- criss-cross attention x2 ----
    float* F = featA;
    float* G = featB;
    for (int it = 0; it < 2; it++) {
        qkv_k<<<dim3(32, BB), 256, QKV_SMEM>>>(F, wq, bq, wk, bk, wv, bv, qb, kb, vb);
        trans_k<<<BB*CQ, 256>>>(kb, ktb);
        trans_k<<<BB*CI, 256>>>(vb, vtb);
        att_k<<<dim3(HH, BB), 256>>>(qb, kb, ktb, attb);
        oH_k<<<dim3(WW, BB), 256, OHW_SMEM>>>(attb, vtb, G);
        oW_k<<<dim3(HH, BB), 256, OHW_SMEM>>>(attb, vb, F, gamma, G);
        float* tmp = F; F = G; G = tmp;
    }
    // after 2 iters: F = featA, G = featB

    // ---- convb (128 -> 128) + BN2 ----
    wprep_k<<<576, 256>>>(convb_w, CI, CI, whi);
    pad_k<<<dim3(64, CI/64, BB), 256>>>(F, CI, x2h, x2l, 128, 0);
    zero_border_k<<<1024, 256>>>(x2h, x2l, 128);
    convmma_k<<<dim3(32, BB), 256, SM_TOTAL>>>(x2h, x2l, 128, CI/64,
                                               whi, CI, CI,
                                               bn2_g, bn2_b, bn2_m, bn2_v,
                                               G, 0);

    // ---- bottleneck conv (concat 512+128 -> 512) + ELU ----
    pad_k<<<dim3(64, CI/64, BB), 256>>>(G, CI, xph, xpl, 640, CIN);
    wprep_k<<<4096, 256>>>(bott_w, CIN, CIN + CI, whi);
    convmma_k<<<dim3(32, BB*(CIN/128)), 256, SM_TOTAL>>>(xph, xpl, 640, (CIN + CI)/64,
                                                         whi, CIN + CI, CIN,
                                                         nullptr, nullptr, nullptr, nullptr,
                                                         out, 1);
}

// round 6
// speedup vs baseline: 13.1463x; 1.3669x over previous
#include <cuda_runtime.h>
#include <cuda_fp16.h>
#include <math.h>
#include <stdint.h>

#define BB 8
#define HH 64
#define WW 64
#define HWSZ 4096
#define CI 128
#define CQ 16
#define CIN 512

// ---------------- scratch buffers (static device allocations) ----------------
__device__ float g_featA[BB*CI*HWSZ];
__device__ float g_featB[BB*CI*HWSZ];
__device__ float g_q [BB*CQ*HWSZ];
__device__ float g_k [BB*CQ*HWSZ];
__device__ float g_kt[BB*CQ*HWSZ];
__device__ float g_v [BB*CI*HWSZ];
__device__ float g_vt[BB*CI*HWSZ];
__device__ float g_att[BB*HH*WW*128];

// padded NHWC fp16 feature maps (16B aligned via uint4)
#define XP640_ELEMS (8ULL*66*66*640)
#define XP128_ELEMS (8ULL*66*66*128)
#define WSP_ELEMS   (9ULL*512*640)
__device__ uint4 g_xph4[XP640_ELEMS/8];
__device__ uint4 g_x2h4[XP128_ELEMS/8];
__device__ uint4 g_whi4[WSP_ELEMS/8];

// =====================================================================
// PTX helpers (compute_103-safe: mma.sync / ldmatrix / cp.async only)
// =====================================================================
__device__ __forceinline__ uint32_t smem_u32(const void* p) {
    uint32_t a;
    asm("{ .reg .u64 t; cvta.to.shared.u64 t, %1; cvt.u32.u64 %0, t; }" : "=r"(a) : "l"(p));
    return a;
}
__device__ __forceinline__ void cpa16(uint32_t dst, const void* src) {
    asm volatile("cp.async.cg.shared.global [%0], [%1], 16;" :: "r"(dst), "l"(src) : "memory");
}
__device__ __forceinline__ void cpa_commit() {
    asm volatile("cp.async.commit_group;" ::: "memory");
}
__device__ __forceinline__ void cpa_wait1() {
    asm volatile("cp.async.wait_group 1;" ::: "memory");
}
__device__ __forceinline__ void cpa_wait0() {
    asm volatile("cp.async.wait_group 0;" ::: "memory");
}
__device__ __forceinline__ void ldsm4(uint32_t* r, uint32_t addr) {
    asm volatile("ldmatrix.sync.aligned.m8n8.x4.shared.b16 {%0,%1,%2,%3}, [%4];"
                 : "=r"(r[0]), "=r"(r[1]), "=r"(r[2]), "=r"(r[3]) : "r"(addr));
}
__device__ __forceinline__ void mma16816(float* c, const uint32_t* a, const uint32_t* b) {
    asm volatile(
        "mma.sync.aligned.m16n8k16.row.col.f32.f16.f16.f32 "
        "{%0,%1,%2,%3}, {%4,%5,%6,%7}, {%8,%9}, {%0,%1,%2,%3};"
        : "+f"(c[0]), "+f"(c[1]), "+f"(c[2]), "+f"(c[3])
        : "r"(a[0]), "r"(a[1]), "r"(a[2]), "r"(a[3]), "r"(b[0]), "r"(b[1]));
}
__device__ __forceinline__ uint32_t sw128(uint32_t off) {
    return off ^ ((off >> 3) & 0x70);
}

// =====================================================================
// prep: NCHW fp32 -> padded NHWC fp16 (interior only)
// =====================================================================
__global__ void __launch_bounds__(256) pad_k(
    const float* __restrict__ src, int C,
    __half* __restrict__ dh, int pitch, int colofs)
{
    __shared__ float s[64][65];
    const int y = blockIdx.x, cbase = blockIdx.y * 64, b = blockIdx.z;
    const int t = threadIdx.x;
    for (int idx = t; idx < 4096; idx += 256) {
        int icl = idx >> 6, x = idx & 63;
        s[icl][x] = src[((size_t)(b*C + cbase + icl)*64 + y)*64 + x];
    }
    __syncthreads();
    for (int idx = t; idx < 4096; idx += 256) {
        int x = idx >> 6, icl = idx & 63;
        size_t o = ((size_t)(b*66 + y + 1)*66 + (x + 1))*pitch + colofs + cbase + icl;
        dh[o] = __float2half_rn(s[icl][x]);
    }
}

__global__ void __launch_bounds__(256) zero_border_k(
    __half* __restrict__ dh, int pitch)
{
    const int total = 8 * 260 * pitch;
    for (int idx = blockIdx.x*256 + threadIdx.x; idx < total; idx += gridDim.x*256) {
        int ic = idx % pitch;
        int r  = idx / pitch;
        int b  = r / 260;
        int pos = r % 260;
        int yy, xx;
        if      (pos < 66)  { yy = 0;  xx = pos; }
        else if (pos < 132) { yy = 65; xx = pos - 66; }
        else if (pos < 196) { yy = pos - 132 + 1; xx = 0; }
        else                { yy = pos - 196 + 1; xx = 65; }
        dh[((size_t)(b*66 + yy)*66 + xx)*pitch + ic] = __float2half_rn(0.f);
    }
}

// weights: w[oc][ic][3][3] fp32 -> Wh [tap][oc][ic] fp16
__global__ void __launch_bounds__(256) wprep_k(
    const float* __restrict__ w, int Cout, int Ctot,
    __half* __restrict__ wh)
{
    const int total = Cout * Ctot * 9;
    for (int idx = blockIdx.x*256 + threadIdx.x; idx < total; idx += gridDim.x*256) {
        int ic  = idx % Ctot;
        int r   = idx / Ctot;
        int oc  = r % Cout;
        int tap = r / Cout;
        wh[(size_t)(tap*Cout + oc)*Ctot + ic] =
            __float2half_rn(w[(size_t)(oc*Ctot + ic)*9 + tap]);
    }
}

// =====================================================================
// HMMA implicit-GEMM conv3x3: CTA tile M=128 oc x N=128 px (2 rows),
// warp tile 64x32, K-chunk = (tap, 64 ic), fp16 x fp16 -> fp32 (1 MMA).
// 128B pitch + sw128 swizzle, 3-stage cp.async ring (wait_group 1),
// launch_bounds(256,2) -> 2 CTAs/SM.
// Epilogue: mode 0 = BN, mode 1 = ELU(512).
// =====================================================================
#define TILE_B (128*128)      // 16384 B per tile (128 rows x 128B)
#define OFF_A  0
#define OFF_B  TILE_B
#define STAGE_B (2*TILE_B)    // 32768 B per stage
#define SM_TOTAL (3*STAGE_B)  // 98304 B

__global__ void __launch_bounds__(256, 2) convmma_k(
    const __half* __restrict__ Xh,
    int pitch, int chunks,
    const __half* __restrict__ Wh,
    int Ctot, int Cout,
    const float* __restrict__ bn_g, const float* __restrict__ bn_b,
    const float* __restrict__ bn_m, const float* __restrict__ bn_v,
    float* __restrict__ out, int mode)
{
    extern __shared__ __align__(128) char smem[];
    const uint32_t sb = smem_u32(smem);
    const int t = threadIdx.x;
    const int warp = t >> 5, lane = t & 31;
    const int nog = Cout >> 7;
    const int ocg = blockIdx.y % nog;
    const int b   = blockIdx.y / nog;
    const int y0  = blockIdx.x * 2;
    const int ocb = ocg * 128;

    const int q8 = t & 7;     // 16B sector (8 fp16)
    const int r0 = t >> 3;    // base row 0..31

    const int T = chunks * 9;

    // ---- async tile loader: tile idx i -> (chunk, tap), stage i%3 ----
    auto issue_tile = [&](int i) {
        const int c   = i / 9;
        const int tap = i - c*9;
        const int dy  = tap / 3, dx = tap - dy*3;
        const int ic0 = c * 64;
        const uint32_t base = sb + (uint32_t)(i % 3) * STAGE_B;
        #pragma unroll
        for (int p = 0; p < 4; p++) {
            const int m = r0 + 32*p;
            const uint32_t so = sw128((uint32_t)(m*128 + q8*16));
            cpa16(base + OFF_A + so,
                  Wh + (size_t)(tap*Cout + ocb + m)*Ctot + ic0 + q8*8);
            const int yl = m >> 6, x = m & 63;
            cpa16(base + OFF_B + so,
                  Xh + ((size_t)(b*66 + y0 + yl + dy)*66 + (x + dx))*pitch + ic0 + q8*8);
        }
        cpa_commit();
    };

    // ---- accumulators ----
    const int m0 = (warp >> 2) * 64;
    const int n0 = (warp & 3) * 32;
    float acc[4][4][4];
    #pragma unroll
    for (int mi = 0; mi < 4; mi++)
        #pragma unroll
        for (int nj = 0; nj < 4; nj++)
            #pragma unroll
            for (int u = 0; u < 4; u++) acc[mi][nj][u] = 0.f;

    const int arow  = lane & 15;
    const int acolb = ((lane >> 4) << 3) * 2;
    const int brow  = (lane & 7) + ((lane >> 4) << 3);
    const int bcolb = (((lane >> 3) & 1) << 3) * 2;

    issue_tile(0);
    if (T > 1) issue_tile(1);

    for (int i = 0; i < T; i++) {
        if (i + 1 < T) cpa_wait1();   // tile i resident, tile i+1 may be in flight
        else           cpa_wait0();
        __syncthreads();              // all warps done with compute(i-1): stage (i+2)%3 free
        if (i + 2 < T) issue_tile(i + 2);

        const uint32_t base = sb + (uint32_t)(i % 3) * STAGE_B;
        const uint32_t sA = base + OFF_A;
        const uint32_t sB = base + OFF_B;

        #pragma unroll
        for (int kk = 0; kk < 4; kk++) {
            const int k0b = kk * 32;   // 16 fp16 = 32 bytes
            uint32_t a[4][4], bh[2][4];
            #pragma unroll
            for (int mi = 0; mi < 4; mi++) {
                const uint32_t ro = sw128((uint32_t)((m0 + mi*16 + arow) * 128 + k0b + acolb));
                ldsm4(a[mi], sA + ro);
            }
            #pragma unroll
            for (int ni = 0; ni < 2; ni++) {
                const uint32_t ro = sw128((uint32_t)((n0 + ni*16 + brow) * 128 + k0b + bcolb));
                ldsm4(bh[ni], sB + ro);
            }
            #pragma unroll
            for (int mi = 0; mi < 4; mi++)
                #pragma unroll
                for (int nj = 0; nj < 4; nj++)
                    mma16816(acc[mi][nj], a[mi], &bh[nj >> 1][(nj & 1) * 2]);
        }
    }

    // ---- epilogue ----
    const int g  = lane >> 2;
    const int t2 = (lane & 3) * 2;
    #pragma unroll
    for (int mi = 0; mi < 4; mi++) {
        const int ocA = ocb + m0 + mi*16 + g;
        const int ocB = ocA + 8;
        float scA = 1.f, biA = 0.f, scB = 1.f, biB = 0.f;
        if (mode == 0) {
            scA = bn_g[ocA] * rsqrtf(bn_v[ocA] + 1e-5f);
            biA = bn_b[ocA] - bn_m[ocA] * scA;
            scB = bn_g[ocB] * rsqrtf(bn_v[ocB] + 1e-5f);
            biB = bn_b[ocB] - bn_m[ocB] * scB;
        }
        #pragma unroll
        for (int nj = 0; nj < 4; nj++) {
            const int n  = n0 + nj*8 + t2;
            const int yl = n >> 6, x = n & 63;
            float v0 = acc[mi][nj][0], v1 = acc[mi][nj][1];
            float v2 = acc[mi][nj][2], v3 = acc[mi][nj][3];
            if (mode == 0) {
                v0 = v0*scA + biA; v1 = v1*scA + biA;
                v2 = v2*scB + biB; v3 = v3*scB + biB;
            } else {
                if (v0 <= 0.f) v0 = 512.0f * expm1f(v0);
                if (v1 <= 0.f) v1 = 512.0f * expm1f(v1);
                if (v2 <= 0.f) v2 = 512.0f * expm1f(v2);
                if (v3 <= 0.f) v3 = 512.0f * expm1f(v3);
            }
            *(float2*)&out[((size_t)(b*Cout + ocA)*64 + y0 + yl)*64 + x] = make_float2(v0, v1);
            *(float2*)&out[((size_t)(b*Cout + ocB)*64 + y0 + yl)*64 + x] = make_float2(v2, v3);
        }
    }
}

// =====================================================================
// attention kernels (fp32 path)
// =====================================================================
__global__ void __launch_bounds__(256) qkv_k(
    const float* __restrict__ feat,
    const float* __restrict__ wq, const float* __restrict__ bq,
    const float* __restrict__ wk, const float* __restrict__ bk,
    const float* __restrict__ wv, const float* __restrict__ bv,
    float* __restrict__ q, float* __restrict__ k, float* __restrict__ v)
{
    extern __shared__ __align__(16) float sm[];
    float* s_in = sm;               // [128 ic][128 px]
    float* s_w  = sm + 128*128;     // [128 ic][pitch 164]

    const int t   = threadIdx.x;
    const int pxb = blockIdx.x * 128;
    const int b   = blockIdx.y;

    const float4* f4 = (const float4*)(feat + (size_t)b*CI*HWSZ);
    for (int idx = t; idx < 128*32; idx += 256) {
        int ic = idx >> 5, p4 = idx & 31;
        ((float4*)s_in)[ic*32 + p4] = f4[ic*(HWSZ/4) + (pxb >> 2) + p4];
    }
    for (int idx = t; idx < 16*128;  idx += 256) { int oc = idx >> 7, ic = idx & 127; s_w[ic*164 + oc]       = wq[idx]; }
    for (int idx = t; idx < 16*128;  idx += 256) { int oc = idx >> 7, ic = idx & 127; s_w[ic*164 + 16 + oc]  = wk[idx]; }
    for (int idx = t; idx < 128*128; idx += 256) { int oc = idx >> 7, ic = idx & 127; s_w[ic*164 + 32 + oc]  = wv[idx]; }
    __syncthreads();

    const int l   = t & 31;
    const int oc0 = (t >> 5) * 20;

    float acc[20][4];
    #pragma unroll
    for (int j = 0; j < 20; j++)
        #pragma unroll
        for (int i = 0; i < 4; i++) acc[j][i] = 0.f;

    for (int ic = 0; ic < 128; ic++) {
        float4 x4 = ((const float4*)s_in)[ic*32 + l];
        const float* wr = s_w + ic*164 + oc0;
        #pragma unroll
        for (int j = 0; j < 5; j++) {
            float4 w4 = *(const float4*)(wr + 4*j);
            acc[4*j+0][0] += w4.x * x4.x; acc[4*j+0][1] += w4.x * x4.y;
            acc[4*j+0][2] += w4.x * x4.z; acc[4*j+0][3] += w4.x * x4.w;
            acc[4*j+1][0] += w4.y * x4.x; acc[4*j+1][1] += w4.y * x4.y;
            acc[4*j+1][2] += w4.y * x4.z; acc[4*j+1][3] += w4.y * x4.w;
            acc[4*j+2][0] += w4.z * x4.x; acc[4*j+2][1] += w4.z * x4.y;
            acc[4*j+2][2] += w4.z * x4.z; acc[4*j+2][3] += w4.z * x4.w;
            acc[4*j+3][0] += w4.w * x4.x; acc[4*j+3][1] += w4.w * x4.y;
            acc[4*j+3][2] += w4.w * x4.z; acc[4*j+3][3] += w4.w * x4.w;
        }
    }

    #pragma unroll
    for (int j = 0; j < 20; j++) {
        const int oc = oc0 + j;
        float bias; float* dst; int o; int C;
        if (oc < 16)      { bias = bq[oc];      dst = q; o = oc;      C = CQ; }
        else if (oc < 32) { bias = bk[oc - 16]; dst = k; o = oc - 16; C = CQ; }
        else              { bias = bv[oc - 32]; dst = v; o = oc - 32; C = CI; }
        *(float4*)&dst[((size_t)b*C + o)*HWSZ + pxb + l*4] =
            make_float4(acc[j][0] + bias, acc[j][1] + bias,
                        acc[j][2] + bias, acc[j][3] + bias);
    }
}

__global__ void __launch_bounds__(256) trans_k(const float* __restrict__ in,
                                               float* __restrict__ out)
{
    __shared__ float s[64][65];
    const float* src = in  + (size_t)blockIdx.x * 4096;
    float*       dst = out + (size_t)blockIdx.x * 4096;
    for (int idx = threadIdx.x; idx < 4096; idx += 256)
        s[idx >> 6][idx & 63] = src[idx];
    __syncthreads();
    for (int idx = threadIdx.x; idx < 4096; idx += 256)
        dst[idx] = s[idx & 63][idx >> 6];
}

__global__ void __launch_bounds__(256) att_k(
    const float* __restrict__ q, const float* __restrict__ k,
    const float* __restrict__ kt, float* __restrict__ att)
{
    __shared__ float qs[16*64];
    __shared__ float ks[16*64];
    __shared__ float E[64*128];

    const int t = threadIdx.x;
    const int h = blockIdx.x, b = blockIdx.y;

    for (int idx = t; idx < 1024; idx += 256) {
        int c = idx >> 6, w = idx & 63;
        qs[idx] = q[((b*CQ + c)*HH + h)*WW + w];
        ks[idx] = k[((b*CQ + c)*HH + h)*WW + w];
    }
    __syncthreads();

    for (int idx = t; idx < 2048; idx += 256) {
        const int w  = idx >> 5;
        const int j4 = idx & 31;
        float4 e = make_float4(0.f, 0.f, 0.f, 0.f);
        if (j4 < 16) {
            for (int c = 0; c < 16; c++) {
                float qq = qs[c*64 + w];
                float4 kv = ((const float4*)kt)[((b*CQ + c)*WW + w)*16 + j4];
                e.x += qq * kv.x; e.y += qq * kv.y; e.z += qq * kv.z; e.w += qq * kv.w;
            }
            if ((h >> 2) == j4) ((float*)&e)[h & 3] = -INFINITY;
        } else {
            for (int c = 0; c < 16; c++) {
                float qq = qs[c*64 + w];
                float4 kv = ((const float4*)ks)[c*16 + (j4 - 16)];
                e.x += qq * kv.x; e.y += qq * kv.y; e.z += qq * kv.z; e.w += qq * kv.w;
            }
        }
        ((float4*)E)[w*32 + j4] = e;
    }
    __syncthreads();

    const int lane = t & 31, wid = t >> 5;
    for (int r = 0; r < 8; r++) {
        const int w = wid*8 + r;
        float v0 = E[w*128 + lane],      v1 = E[w*128 + lane + 32];
        float v2 = E[w*128 + lane + 64], v3 = E[w*128 + lane + 96];
        float m = fmaxf(fmaxf(v0, v1), fmaxf(v2, v3));
        #pragma unroll
        for (int s = 16; s; s >>= 1) m = fmaxf(m, __shfl_xor_sync(0xffffffffu, m, s));
        float e0 = expf(v0 - m), e1 = expf(v1 - m), e2 = expf(v2 - m), e3 = expf(v3 - m);
        float sum = e0 + e1 + e2 + e3;
        #pragma unroll
        for (int s = 16; s; s >>= 1) sum += __shfl_xor_sync(0xffffffffu, sum, s);
        float inv = 1.f / sum;
        float* dst = att + (size_t)((b*HH + h)*WW + w)*128;
        dst[lane] = e0*inv; dst[lane+32] = e1*inv; dst[lane+64] = e2*inv; dst[lane+96] = e3*inv;
    }
}

__global__ void __launch_bounds__(256) oH_k(
    const float* __restrict__ att, const float* __restrict__ vt,
    float* __restrict__ outb)
{
    extern __shared__ __align__(16) float sm[];
    float* As = sm;
    float* Vs = sm + 64*68;

    const int t = threadIdx.x;
    const int w = blockIdx.x, b = blockIdx.y;

    for (int idx = t; idx < 4096; idx += 256) {
        int hh = idx >> 6, g = idx & 63;
        As[g*68 + hh] = att[(size_t)((b*HH + hh)*WW + w)*128 + g];
    }
    for (int idx = t; idx < 8192; idx += 256) {
        int c = idx >> 6, g = idx & 63;
        Vs[g*132 + c] = vt[((b*CI + c)*WW + w)*HH + g];
    }
    __syncthreads();

    const int c0 = (t & 31) * 4;
    const int h0 = (t >> 5) * 8;
    float acc[8][4];
    #pragma unroll
    for (int i = 0; i < 8; i++)
        #pragma unroll
        for (int j = 0; j < 4; j++) acc[i][j] = 0.f;

    for (int g = 0; g < 64; g++) {
        float4 v4 = *(const float4*)&Vs[g*132 + c0];
        #pragma unroll
        for (int hi = 0; hi < 8; hi++) {
            float av = As[g*68 + h0 + hi];
            acc[hi][0] += av * v4.x; acc[hi][1] += av * v4.y;
            acc[hi][2] += av * v4.z; acc[hi][3] += av * v4.w;
        }
    }
    #pragma unroll
    for (int hi = 0; hi < 8; hi++)
        #pragma unroll
        for (int ci = 0; ci < 4; ci++)
            outb[((b*CI + c0 + ci)*HH + h0 + hi)*WW + w] = acc[hi][ci];
}

__global__ void __launch_bounds__(256) oW_k(
    const float* __restrict__ att, const float* __restrict__ v,
    const float* __restrict__ feat, const float* __restrict__ gamma,
    float* __restrict__ outb)
{
    extern __shared__ __align__(16) float sm[];
    float* Aw = sm;
    float* Ws = sm + 64*68;

    const int t = threadIdx.x;
    const int h = blockIdx.x, b = blockIdx.y;

    for (int idx = t; idx < 4096; idx += 256) {
        int w = idx >> 6, wp = idx & 63;
        Aw[wp*68 + w] = att[(size_t)((b*HH + h)*WW + w)*128 + 64 + wp];
    }
    for (int idx = t; idx < 8192; idx += 256) {
        int c = idx >> 6, wp = idx & 63;
        Ws[wp*132 + c] = v[((b*CI + c)*HH + h)*WW + wp];
    }
    __syncthreads();

    const int c0 = (t & 31) * 4;
    const int w0 = (t >> 5) * 8;
    float acc[8][4];
    #pragma unroll
    for (int i = 0; i < 8; i++)
        #pragma unroll
        for (int j = 0; j < 4; j++) acc[i][j] = 0.f;

    for (int wp = 0; wp < 64; wp++) {
        float4 v4 = *(const float4*)&Ws[wp*132 + c0];
        #pragma unroll
        for (int wi = 0; wi < 8; wi++) {
            float av = Aw[wp*68 + w0 + wi];
            acc[wi][0] += av * v4.x; acc[wi][1] += av * v4.y;
            acc[wi][2] += av * v4.z; acc[wi][3] += av * v4.w;
        }
    }

    const float g = gamma[0];
    #pragma unroll
    for (int ci = 0; ci < 4; ci++) {
        const int base = ((b*CI + c0 + ci)*HH + h)*WW + w0;
        float4 f0 = *(const float4*)&feat[base];
        float4 f1 = *(const float4*)&feat[base + 4];
        float4 o0 = *(const float4*)&outb[base];
        float4 o1 = *(const float4*)&outb[base + 4];
        float4 r0 = make_float4(f0.x + g*(o0.x + acc[0][ci]),
                                f0.y + g*(o0.y + acc[1][ci]),
                                f0.z + g*(o0.z + acc[2][ci]),
                                f0.w + g*(o0.w + acc[3][ci]));
        float4 r1 = make_float4(f1.x + g*(o1.x + acc[4][ci]),
                                f1.y + g*(o1.y + acc[5][ci]),
                                f1.z + g*(o1.z + acc[6][ci]),
                                f1.w + g*(o1.w + acc[7][ci]));
        *(float4*)&outb[base]     = r0;
        *(float4*)&outb[base + 4] = r1;
    }
}

// =====================================================================
extern "C" void kernel_launch(void* const* d_in, const int* in_sizes, int n_in,
                              void* d_out, int out_size)
{
    (void)in_sizes; (void)n_in; (void)out_size;
    const float* x       = (const float*)d_in[0];
    const float* conva_w = (const float*)d_in[1];
    const float* bn1_g   = (const float*)d_in[2];
    const float* bn1_b   = (const float*)d_in[3];
    const float* bn1_m   = (const float*)d_in[4];
    const float* bn1_v   = (const float*)d_in[5];
    const float* wq      = (const float*)d_in[6];
    const float* bq      = (const float*)d_in[7];
    const float* wk      = (const float*)d_in[8];
    const float* bk      = (const float*)d_in[9];
    const float* wv      = (const float*)d_in[10];
    const float* bv      = (const float*)d_in[11];
    const float* gamma   = (const float*)d_in[12];
    const float* convb_w = (const float*)d_in[13];
    const float* bn2_g   = (const float*)d_in[14];
    const float* bn2_b   = (const float*)d_in[15];
    const float* bn2_m   = (const float*)d_in[16];
    const float* bn2_v   = (const float*)d_in[17];
    const float* bott_w  = (const float*)d_in[18];
    float* out = (float*)d_out;

    float *featA, *featB, *qb, *kb, *ktb, *vb, *vtb, *attb;
    cudaGetSymbolAddress((void**)&featA, g_featA);
    cudaGetSymbolAddress((void**)&featB, g_featB);
    cudaGetSymbolAddress((void**)&qb,    g_q);
    cudaGetSymbolAddress((void**)&kb,    g_k);
    cudaGetSymbolAddress((void**)&ktb,   g_kt);
    cudaGetSymbolAddress((void**)&vb,    g_v);
    cudaGetSymbolAddress((void**)&vtb,   g_vt);
    cudaGetSymbolAddress((void**)&attb,  g_att);

    __half *xph, *x2h, *whi;
    cudaGetSymbolAddress((void**)&xph, g_xph4);
    cudaGetSymbolAddress((void**)&x2h, g_x2h4);
    cudaGetSymbolAddress((void**)&whi, g_whi4);

    const int QKV_SMEM = (128*128 + 128*164) * 4;
    const int OHW_SMEM = (64*68 + 64*132) * 4;
    cudaFuncSetAttribute(qkv_k,     cudaFuncAttributeMaxDynamicSharedMemorySize, QKV_SMEM);
    cudaFuncSetAttribute(oH_k,      cudaFuncAttributeMaxDynamicSharedMemorySize, OHW_SMEM);
    cudaFuncSetAttribute(oW_k,      cudaFuncAttributeMaxDynamicSharedMemorySize, OHW_SMEM);
    cudaFuncSetAttribute(convmma_k, cudaFuncAttributeMaxDynamicSharedMemorySize, SM_TOTAL);

    // ---- conv1 (512 -> 128) + BN1 ----
    wprep_k<<<512, 256>>>(conva_w, CI, CIN, whi);
    pad_k<<<dim3(64, CIN/64, BB), 256>>>(x, CIN, xph, 640, 0);
    zero_border_k<<<1024, 256>>>(xph, 640);
    convmma_k<<<dim3(32, BB), 256, SM_TOTAL>>>(xph, 640, CIN/64,
                                               whi, CIN, CI,
                                               bn1_g, bn1_b, bn1_m, bn1_v,
                                               featA, 0);

    // ---- criss-cross attention x2 ----
    float* F = featA;
    float* G = featB;
    for (int it = 0; it < 2; it++) {
        qkv_k<<<dim3(32, BB), 256, QKV_SMEM>>>(F, wq, bq, wk, bk, wv, bv, qb, kb, vb);
        trans_k<<<BB*CQ, 256>>>(kb, ktb);
        trans_k<<<BB*CI, 256>>>(vb, vtb);
        att_k<<<dim3(HH, BB), 256>>>(qb, kb, ktb, attb);
        oH_k<<<dim3(WW, BB), 256, OHW_SMEM>>>(attb, vtb, G);
        oW_k<<<dim3(HH, BB), 256, OHW_SMEM>>>(attb, vb, F, gamma, G);
        float* tmp = F; F = G; G = tmp;
    }
    // after 2 iters: F = featA, G = featB

    // ---- convb (128 -> 128) + BN2 ----
    wprep_k<<<576, 256>>>(convb_w, CI, CI, whi);
    pad_k<<<dim3(64, CI/64, BB), 256>>>(F, CI, x2h, 128, 0);
    zero_border_k<<<1024, 256>>>(x2h, 128);
    convmma_k<<<dim3(32, BB), 256, SM_TOTAL>>>(x2h, 128, CI/64,
                                               whi, CI, CI,
                                               bn2_g, bn2_b, bn2_m, bn2_v,
                                               G, 0);

    // ---- bottleneck conv (concat 512+128 -> 512) + ELU ----
    pad_k<<<dim3(64, CI/64, BB), 256>>>(G, CI, xph, 640, CIN);
    wprep_k<<<4096, 256>>>(bott_w, CIN, CIN + CI, whi);
    convmma_k<<<dim3(32, BB*(CIN/128)), 256, SM_TOTAL>>>(xph, 640, (CIN + CI)/64,
                                                         whi, CIN + CI, CIN,
                                                         nullptr, nullptr, nullptr, nullptr,
                                                         out, 1);
}

// round 7
// speedup vs baseline: 13.3451x; 1.0151x over previous
#include <cuda_runtime.h>
#include <cuda_fp16.h>
#include <math.h>
#include <stdint.h>

#define BB 8
#define HH 64
#define WW 64
#define HWSZ 4096
#define CI 128
#define CQ 16
#define CIN 512

// ---------------- scratch buffers (static device allocations) ----------------
__device__ float g_featA[BB*CI*HWSZ];
__device__ float g_featB[BB*CI*HWSZ];
__device__ float g_q [BB*CQ*HWSZ];
__device__ float g_k [BB*CQ*HWSZ];
__device__ float g_kt[BB*CQ*HWSZ];
__device__ float g_v [BB*CI*HWSZ];
__device__ float g_vt[BB*CI*HWSZ];
__device__ float g_att[BB*HH*WW*128];

// padded NHWC fp16 feature maps (16B aligned via uint4)
#define XP640_ELEMS (8ULL*66*66*640)
#define XP128_ELEMS (8ULL*66*66*128)
#define WSP_ELEMS   (9ULL*512*640)
__device__ uint4 g_xph4[XP640_ELEMS/8];
__device__ uint4 g_x2h4[XP128_ELEMS/8];
__device__ uint4 g_whi4[WSP_ELEMS/8];
__device__ uint4 g_wqkv4[(256*128)/8];   // packed q|k|v|pad weights, fp16

// =====================================================================
// PTX helpers (compute_103-safe: mma.sync / ldmatrix / cp.async only)
// =====================================================================
__device__ __forceinline__ uint32_t smem_u32(const void* p) {
    uint32_t a;
    asm("{ .reg .u64 t; cvta.to.shared.u64 t, %1; cvt.u32.u64 %0, t; }" : "=r"(a) : "l"(p));
    return a;
}
__device__ __forceinline__ void cpa16(uint32_t dst, const void* src) {
    asm volatile("cp.async.cg.shared.global [%0], [%1], 16;" :: "r"(dst), "l"(src) : "memory");
}
__device__ __forceinline__ void cpa_commit() {
    asm volatile("cp.async.commit_group;" ::: "memory");
}
__device__ __forceinline__ void cpa_wait1() {
    asm volatile("cp.async.wait_group 1;" ::: "memory");
}
__device__ __forceinline__ void cpa_wait0() {
    asm volatile("cp.async.wait_group 0;" ::: "memory");
}
__device__ __forceinline__ void ldsm4(uint32_t* r, uint32_t addr) {
    asm volatile("ldmatrix.sync.aligned.m8n8.x4.shared.b16 {%0,%1,%2,%3}, [%4];"
                 : "=r"(r[0]), "=r"(r[1]), "=r"(r[2]), "=r"(r[3]) : "r"(addr));
}
__device__ __forceinline__ void mma16816(float* c, const uint32_t* a, const uint32_t* b) {
    asm volatile(
        "mma.sync.aligned.m16n8k16.row.col.f32.f16.f16.f32 "
        "{%0,%1,%2,%3}, {%4,%5,%6,%7}, {%8,%9}, {%0,%1,%2,%3};"
        : "+f"(c[0]), "+f"(c[1]), "+f"(c[2]), "+f"(c[3])
        : "r"(a[0]), "r"(a[1]), "r"(a[2]), "r"(a[3]), "r"(b[0]), "r"(b[1]));
}
__device__ __forceinline__ uint32_t sw128(uint32_t off) {
    return off ^ ((off >> 3) & 0x70);
}

// =====================================================================
// prep: NCHW fp32 -> padded NHWC fp16 (interior only)
// =====================================================================
__global__ void __launch_bounds__(256) pad_k(
    const float* __restrict__ src, int C,
    __half* __restrict__ dh, int pitch, int colofs)
{
    __shared__ float s[64][65];
    const int y = blockIdx.x, cbase = blockIdx.y * 64, b = blockIdx.z;
    const int t = threadIdx.x;
    for (int idx = t; idx < 4096; idx += 256) {
        int icl = idx >> 6, x = idx & 63;
        s[icl][x] = src[((size_t)(b*C + cbase + icl)*64 + y)*64 + x];
    }
    __syncthreads();
    for (int idx = t; idx < 4096; idx += 256) {
        int x = idx >> 6, icl = idx & 63;
        size_t o = ((size_t)(b*66 + y + 1)*66 + (x + 1))*pitch + colofs + cbase + icl;
        dh[o] = __float2half_rn(s[icl][x]);
    }
}

__global__ void __launch_bounds__(256) zero_border_k(
    __half* __restrict__ dh, int pitch)
{
    const int total = 8 * 260 * pitch;
    for (int idx = blockIdx.x*256 + threadIdx.x; idx < total; idx += gridDim.x*256) {
        int ic = idx % pitch;
        int r  = idx / pitch;
        int b  = r / 260;
        int pos = r % 260;
        int yy, xx;
        if      (pos < 66)  { yy = 0;  xx = pos; }
        else if (pos < 132) { yy = 65; xx = pos - 66; }
        else if (pos < 196) { yy = pos - 132 + 1; xx = 0; }
        else                { yy = pos - 196 + 1; xx = 65; }
        dh[((size_t)(b*66 + yy)*66 + xx)*pitch + ic] = __float2half_rn(0.f);
    }
}

// weights: w[oc][ic][3][3] fp32 -> Wh [tap][oc][ic] fp16
__global__ void __launch_bounds__(256) wprep_k(
    const float* __restrict__ w, int Cout, int Ctot,
    __half* __restrict__ wh)
{
    const int total = Cout * Ctot * 9;
    for (int idx = blockIdx.x*256 + threadIdx.x; idx < total; idx += gridDim.x*256) {
        int ic  = idx % Ctot;
        int r   = idx / Ctot;
        int oc  = r % Cout;
        int tap = r / Cout;
        wh[(size_t)(tap*Cout + oc)*Ctot + ic] =
            __float2half_rn(w[(size_t)(oc*Ctot + ic)*9 + tap]);
    }
}

// packed qkv weights: [256 oc][128 ic] fp16 = q(16) | k(16) | v(128) | zeros(96)
__global__ void __launch_bounds__(256) wprep_qkv_k(
    const float* __restrict__ wq, const float* __restrict__ wk,
    const float* __restrict__ wv, __half* __restrict__ wh)
{
    const int total = 256 * 128;
    for (int idx = blockIdx.x*256 + threadIdx.x; idx < total; idx += gridDim.x*256) {
        int oc = idx >> 7, ic = idx & 127;
        float v = 0.f;
        if      (oc < 16)  v = wq[oc*128 + ic];
        else if (oc < 32)  v = wk[(oc-16)*128 + ic];
        else if (oc < 160) v = wv[(oc-32)*128 + ic];
        wh[idx] = __float2half_rn(v);
    }
}

// =====================================================================
// HMMA implicit-GEMM conv: CTA tile M=128 oc x N=128 px (2 rows),
// warp tile 64x32, K-chunk = (tap, 64 ic), fp16 x fp16 -> fp32.
// ntap = 9 (3x3) or 1 (1x1, center tap).
// Epilogue: mode 0 = BN, mode 1 = ELU(512),
//           mode 3 = qkv scatter (bias in bn_g/bn_b/bn_m; out=q, out2=k,
//                    out3=v, out3t=v transposed)
// =====================================================================
#define TILE_B (128*128)      // 16384 B per tile (128 rows x 128B)
#define OFF_A  0
#define OFF_B  TILE_B
#define STAGE_B (2*TILE_B)    // 32768 B per stage
#define SM_TOTAL (3*STAGE_B)  // 98304 B

__global__ void __launch_bounds__(256, 2) convmma_k(
    const __half* __restrict__ Xh,
    int pitch, int chunks, int ntap,
    const __half* __restrict__ Wh,
    int Ctot, int Cout,
    const float* __restrict__ bn_g, const float* __restrict__ bn_b,
    const float* __restrict__ bn_m, const float* __restrict__ bn_v,
    float* __restrict__ out, int mode,
    float* __restrict__ out2, float* __restrict__ out3,
    float* __restrict__ out3t)
{
    extern __shared__ __align__(128) char smem[];
    const uint32_t sb = smem_u32(smem);
    const int t = threadIdx.x;
    const int warp = t >> 5, lane = t & 31;
    const int nog = Cout >> 7;
    const int ocg = blockIdx.y % nog;
    const int b   = blockIdx.y / nog;
    const int y0  = blockIdx.x * 2;
    const int ocb = ocg * 128;

    const int q8 = t & 7;     // 16B sector (8 fp16)
    const int r0 = t >> 3;    // base row 0..31

    const int T = chunks * ntap;

    // ---- async tile loader: tile idx i -> (chunk, tap), stage i%3 ----
    auto issue_tile = [&](int i) {
        const int c   = i / ntap;
        const int tap = i - c*ntap;
        const int dy  = (ntap == 1) ? 1 : tap / 3;
        const int dx  = (ntap == 1) ? 1 : tap - (tap/3)*3;
        const int ic0 = c * 64;
        const uint32_t base = sb + (uint32_t)(i % 3) * STAGE_B;
        #pragma unroll
        for (int p = 0; p < 4; p++) {
            const int m = r0 + 32*p;
            const uint32_t so = sw128((uint32_t)(m*128 + q8*16));
            cpa16(base + OFF_A + so,
                  Wh + (size_t)(tap*Cout + ocb + m)*Ctot + ic0 + q8*8);
            const int yl = m >> 6, x = m & 63;
            cpa16(base + OFF_B + so,
                  Xh + ((size_t)(b*66 + y0 + yl + dy)*66 + (x + dx))*pitch + ic0 + q8*8);
        }
        cpa_commit();
    };

    // ---- accumulators ----
    const int m0 = (warp >> 2) * 64;
    const int n0 = (warp & 3) * 32;
    float acc[4][4][4];
    #pragma unroll
    for (int mi = 0; mi < 4; mi++)
        #pragma unroll
        for (int nj = 0; nj < 4; nj++)
            #pragma unroll
            for (int u = 0; u < 4; u++) acc[mi][nj][u] = 0.f;

    const int arow  = lane & 15;
    const int acolb = ((lane >> 4) << 3) * 2;
    const int brow  = (lane & 7) + ((lane >> 4) << 3);
    const int bcolb = (((lane >> 3) & 1) << 3) * 2;

    issue_tile(0);
    if (T > 1) issue_tile(1);

    for (int i = 0; i < T; i++) {
        if (i + 1 < T) cpa_wait1();
        else           cpa_wait0();
        __syncthreads();
        if (i + 2 < T) issue_tile(i + 2);

        const uint32_t base = sb + (uint32_t)(i % 3) * STAGE_B;
        const uint32_t sA = base + OFF_A;
        const uint32_t sB = base + OFF_B;

        #pragma unroll
        for (int kk = 0; kk < 4; kk++) {
            const int k0b = kk * 32;
            uint32_t a[4][4], bh[2][4];
            #pragma unroll
            for (int mi = 0; mi < 4; mi++) {
                const uint32_t ro = sw128((uint32_t)((m0 + mi*16 + arow) * 128 + k0b + acolb));
                ldsm4(a[mi], sA + ro);
            }
            #pragma unroll
            for (int ni = 0; ni < 2; ni++) {
                const uint32_t ro = sw128((uint32_t)((n0 + ni*16 + brow) * 128 + k0b + bcolb));
                ldsm4(bh[ni], sB + ro);
            }
            #pragma unroll
            for (int mi = 0; mi < 4; mi++)
                #pragma unroll
                for (int nj = 0; nj < 4; nj++)
                    mma16816(acc[mi][nj], a[mi], &bh[nj >> 1][(nj & 1) * 2]);
        }
    }

    // ---- epilogue ----
    const int g  = lane >> 2;
    const int t2 = (lane & 3) * 2;
    #pragma unroll
    for (int mi = 0; mi < 4; mi++) {
        const int ocA = ocb + m0 + mi*16 + g;
        const int ocB = ocA + 8;
        float scA = 1.f, biA = 0.f, scB = 1.f, biB = 0.f;
        if (mode == 0) {
            scA = bn_g[ocA] * rsqrtf(bn_v[ocA] + 1e-5f);
            biA = bn_b[ocA] - bn_m[ocA] * scA;
            scB = bn_g[ocB] * rsqrtf(bn_v[ocB] + 1e-5f);
            biB = bn_b[ocB] - bn_m[ocB] * scB;
        }
        #pragma unroll
        for (int nj = 0; nj < 4; nj++) {
            const int n  = n0 + nj*8 + t2;
            const int yl = n >> 6, x = n & 63;
            const int py = y0 + yl;
            float v0 = acc[mi][nj][0], v1 = acc[mi][nj][1];
            float v2 = acc[mi][nj][2], v3 = acc[mi][nj][3];
            if (mode == 3) {
                // qkv scatter: oc<16 -> q (+bn_g bias), <32 -> k (+bn_b),
                // <160 -> v (+bn_m) + transposed copy, else discard.
                #pragma unroll
                for (int h = 0; h < 2; h++) {
                    const int oc = h ? ocB : ocA;
                    float u0 = h ? v2 : v0;
                    float u1 = h ? v3 : v1;
                    if (oc < 16) {
                        float bi = bn_g[oc];
                        *(float2*)&out[((size_t)(b*CQ + oc)*64 + py)*64 + x] =
                            make_float2(u0 + bi, u1 + bi);
                    } else if (oc < 32) {
                        float bi = bn_b[oc - 16];
                        *(float2*)&out2[((size_t)(b*CQ + oc - 16)*64 + py)*64 + x] =
                            make_float2(u0 + bi, u1 + bi);
                    } else if (oc < 160) {
                        const int c = oc - 32;
                        float bi = bn_m[c];
                        u0 += bi; u1 += bi;
                        *(float2*)&out3[((size_t)(b*CI + c)*64 + py)*64 + x] =
                            make_float2(u0, u1);
                        out3t[((size_t)(b*CI + c)*64 + x    )*64 + py] = u0;
                        out3t[((size_t)(b*CI + c)*64 + x + 1)*64 + py] = u1;
                    }
                }
                continue;
            }
            if (mode == 0) {
                v0 = v0*scA + biA; v1 = v1*scA + biA;
                v2 = v2*scB + biB; v3 = v3*scB + biB;
            } else {
                if (v0 <= 0.f) v0 = 512.0f * expm1f(v0);
                if (v1 <= 0.f) v1 = 512.0f * expm1f(v1);
                if (v2 <= 0.f) v2 = 512.0f * expm1f(v2);
                if (v3 <= 0.f) v3 = 512.0f * expm1f(v3);
            }
            *(float2*)&out[((size_t)(b*Cout + ocA)*64 + py)*64 + x] = make_float2(v0, v1);
            *(float2*)&out[((size_t)(b*Cout + ocB)*64 + py)*64 + x] = make_float2(v2, v3);
        }
    }
}

// =====================================================================
// attention kernels (fp32 path)
// =====================================================================
__global__ void __launch_bounds__(256) trans_k(const float* __restrict__ in,
                                               float* __restrict__ out)
{
    __shared__ float s[64][65];
    const float* src = in  + (size_t)blockIdx.x * 4096;
    float*       dst = out + (size_t)blockIdx.x * 4096;
    for (int idx = threadIdx.x; idx < 4096; idx += 256)
        s[idx >> 6][idx & 63] = src[idx];
    __syncthreads();
    for (int idx = threadIdx.x; idx < 4096; idx += 256)
        dst[idx] = s[idx & 63][idx >> 6];
}

__global__ void __launch_bounds__(256) att_k(
    const float* __restrict__ q, const float* __restrict__ k,
    const float* __restrict__ kt, float* __restrict__ att)
{
    __shared__ float qs[16*64];
    __shared__ float ks[16*64];
    __shared__ float E[64*128];

    const int t = threadIdx.x;
    const int h = blockIdx.x, b = blockIdx.y;

    for (int idx = t; idx < 1024; idx += 256) {
        int c = idx >> 6, w = idx & 63;
        qs[idx] = q[((b*CQ + c)*HH + h)*WW + w];
        ks[idx] = k[((b*CQ + c)*HH + h)*WW + w];
    }
    __syncthreads();

    for (int idx = t; idx < 2048; idx += 256) {
        const int w  = idx >> 5;
        const int j4 = idx & 31;
        float4 e = make_float4(0.f, 0.f, 0.f, 0.f);
        if (j4 < 16) {
            for (int c = 0; c < 16; c++) {
                float qq = qs[c*64 + w];
                float4 kv = ((const float4*)kt)[((b*CQ + c)*WW + w)*16 + j4];
                e.x += qq * kv.x; e.y += qq * kv.y; e.z += qq * kv.z; e.w += qq * kv.w;
            }
            if ((h >> 2) == j4) ((float*)&e)[h & 3] = -INFINITY;
        } else {
            for (int c = 0; c < 16; c++) {
                float qq = qs[c*64 + w];
                float4 kv = ((const float4*)ks)[c*16 + (j4 - 16)];
                e.x += qq * kv.x; e.y += qq * kv.y; e.z += qq * kv.z; e.w += qq * kv.w;
            }
        }
        ((float4*)E)[w*32 + j4] = e;
    }
    __syncthreads();

    const int lane = t & 31, wid = t >> 5;
    for (int r = 0; r < 8; r++) {
        const int w = wid*8 + r;
        float v0 = E[w*128 + lane],      v1 = E[w*128 + lane + 32];
        float v2 = E[w*128 + lane + 64], v3 = E[w*128 + lane + 96];
        float m = fmaxf(fmaxf(v0, v1), fmaxf(v2, v3));
        #pragma unroll
        for (int s = 16; s; s >>= 1) m = fmaxf(m, __shfl_xor_sync(0xffffffffu, m, s));
        float e0 = expf(v0 - m), e1 = expf(v1 - m), e2 = expf(v2 - m), e3 = expf(v3 - m);
        float sum = e0 + e1 + e2 + e3;
        #pragma unroll
        for (int s = 16; s; s >>= 1) sum += __shfl_xor_sync(0xffffffffu, sum, s);
        float inv = 1.f / sum;
        float* dst = att + (size_t)((b*HH + h)*WW + w)*128;
        dst[lane] = e0*inv; dst[lane+32] = e1*inv; dst[lane+64] = e2*inv; dst[lane+96] = e3*inv;
    }
}

__global__ void __launch_bounds__(256) oH_k(
    const float* __restrict__ att, const float* __restrict__ vt,
    float* __restrict__ outb)
{
    extern __shared__ __align__(16) float sm[];
    float* As = sm;
    float* Vs = sm + 64*68;

    const int t = threadIdx.x;
    const int w = blockIdx.x, b = blockIdx.y;

    for (int idx = t; idx < 4096; idx += 256) {
        int hh = idx >> 6, g = idx & 63;
        As[g*68 + hh] = att[(size_t)((b*HH + hh)*WW + w)*128 + g];
    }
    for (int idx = t; idx < 8192; idx += 256) {
        int c = idx >> 6, g = idx & 63;
        Vs[g*132 + c] = vt[((b*CI + c)*WW + w)*HH + g];
    }
    __syncthreads();

    const int c0 = (t & 31) * 4;
    const int h0 = (t >> 5) * 8;
    float acc[8][4];
    #pragma unroll
    for (int i = 0; i < 8; i++)
        #pragma unroll
        for (int j = 0; j < 4; j++) acc[i][j] = 0.f;

    for (int g = 0; g < 64; g++) {
        float4 v4 = *(const float4*)&Vs[g*132 + c0];
        #pragma unroll
        for (int hi = 0; hi < 8; hi++) {
            float av = As[g*68 + h0 + hi];
            acc[hi][0] += av * v4.x; acc[hi][1] += av * v4.y;
            acc[hi][2] += av * v4.z; acc[hi][3] += av * v4.w;
        }
    }
    #pragma unroll
    for (int hi = 0; hi < 8; hi++)
        #pragma unroll
        for (int ci = 0; ci < 4; ci++)
            outb[((b*CI + c0 + ci)*HH + h0 + hi)*WW + w] = acc[hi][ci];
}

__global__ void __launch_bounds__(256) oW_k(
    const float* __restrict__ att, const float* __restrict__ v,
    const float* __restrict__ feat, const float* __restrict__ gamma,
    float* __restrict__ outb)
{
    extern __shared__ __align__(16) float sm[];
    float* Aw = sm;
    float* Ws = sm + 64*68;

    const int t = threadIdx.x;
    const int h = blockIdx.x, b = blockIdx.y;

    for (int idx = t; idx < 4096; idx += 256) {
        int w = idx >> 6, wp = idx & 63;
        Aw[wp*68 + w] = att[(size_t)((b*HH + h)*WW + w)*128 + 64 + wp];
    }
    for (int idx = t; idx < 8192; idx += 256) {
        int c = idx >> 6, wp = idx & 63;
        Ws[wp*132 + c] = v[((b*CI + c)*HH + h)*WW + wp];
    }
    __syncthreads();

    const int c0 = (t & 31) * 4;
    const int w0 = (t >> 5) * 8;
    float acc[8][4];
    #pragma unroll
    for (int i = 0; i < 8; i++)
        #pragma unroll
        for (int j = 0; j < 4; j++) acc[i][j] = 0.f;

    for (int wp = 0; wp < 64; wp++) {
        float4 v4 = *(const float4*)&Ws[wp*132 + c0];
        #pragma unroll
        for (int wi = 0; wi < 8; wi++) {
            float av = Aw[wp*68 + w0 + wi];
            acc[wi][0] += av * v4.x; acc[wi][1] += av * v4.y;
            acc[wi][2] += av * v4.z; acc[wi][3] += av * v4.w;
        }
    }

    const float g = gamma[0];
    #pragma unroll
    for (int ci = 0; ci < 4; ci++) {
        const int base = ((b*CI + c0 + ci)*HH + h)*WW + w0;
        float4 f0 = *(const float4*)&feat[base];
        float4 f1 = *(const float4*)&feat[base + 4];
        float4 o0 = *(const float4*)&outb[base];
        float4 o1 = *(const float4*)&outb[base + 4];
        float4 r0 = make_float4(f0.x + g*(o0.x + acc[0][ci]),
                                f0.y + g*(o0.y + acc[1][ci]),
                                f0.z + g*(o0.z + acc[2][ci]),
                                f0.w + g*(o0.w + acc[3][ci]));
        float4 r1 = make_float4(f1.x + g*(o1.x + acc[4][ci]),
                                f1.y + g*(o1.y + acc[5][ci]),
                                f1.z + g*(o1.z + acc[6][ci]),
                                f1.w + g*(o1.w + acc[7][ci]));
        *(float4*)&outb[base]     = r0;
        *(float4*)&outb[base + 4] = r1;
    }
}

// =====================================================================
extern "C" void kernel_launch(void* const* d_in, const int* in_sizes, int n_in,
                              void* d_out, int out_size)
{
    (void)in_sizes; (void)n_in; (void)out_size;
    const float* x       = (const float*)d_in[0];
    const float* conva_w = (const float*)d_in[1];
    const float* bn1_g   = (const float*)d_in[2];
    const float* bn1_b   = (const float*)d_in[3];
    const float* bn1_m   = (const float*)d_in[4];
    const float* bn1_v   = (const float*)d_in[5];
    const float* wq      = (const float*)d_in[6];
    const float* bq      = (const float*)d_in[7];
    const float* wk      = (const float*)d_in[8];
    const float* bk      = (const float*)d_in[9];
    const float* wv      = (const float*)d_in[10];
    const float* bv      = (const float*)d_in[11];
    const float* gamma   = (const float*)d_in[12];
    const float* convb_w = (const float*)d_in[13];
    const float* bn2_g   = (const float*)d_in[14];
    const float* bn2_b   = (const float*)d_in[15];
    const float* bn2_m   = (const float*)d_in[16];
    const float* bn2_v   = (const float*)d_in[17];
    const float* bott_w  = (const float*)d_in[18];
    float* out = (float*)d_out;

    float *featA, *featB, *qb, *kb, *ktb, *vb, *vtb, *attb;
    cudaGetSymbolAddress((void**)&featA, g_featA);
    cudaGetSymbolAddress((void**)&featB, g_featB);
    cudaGetSymbolAddress((void**)&qb,    g_q);
    cudaGetSymbolAddress((void**)&kb,    g_k);
    cudaGetSymbolAddress((void**)&ktb,   g_kt);
    cudaGetSymbolAddress((void**)&vb,    g_v);
    cudaGetSymbolAddress((void**)&vtb,   g_vt);
    cudaGetSymbolAddress((void**)&attb,  g_att);

    __half *xph, *x2h, *whi, *wqkv;
    cudaGetSymbolAddress((void**)&xph,  g_xph4);
    cudaGetSymbolAddress((void**)&x2h,  g_x2h4);
    cudaGetSymbolAddress((void**)&whi,  g_whi4);
    cudaGetSymbolAddress((void**)&wqkv, g_wqkv4);

    const int OHW_SMEM = (64*68 + 64*132) * 4;
    cudaFuncSetAttribute(oH_k,      cudaFuncAttributeMaxDynamicSharedMemorySize, OHW_SMEM);
    cudaFuncSetAttribute(oW_k,      cudaFuncAttributeMaxDynamicSharedMemorySize, OHW_SMEM);
    cudaFuncSetAttribute(convmma_k, cudaFuncAttributeMaxDynamicSharedMemorySize, SM_TOTAL);

    // ---- conv1 (512 -> 128) + BN1 ----
    wprep_k<<<512, 256>>>(conva_w, CI, CIN, whi);
    pad_k<<<dim3(64, CIN/64, BB), 256>>>(x, CIN, xph, 640, 0);
    zero_border_k<<<1024, 256>>>(xph, 640);
    convmma_k<<<dim3(32, BB), 256, SM_TOTAL>>>(xph, 640, CIN/64, 9,
                                               whi, CIN, CI,
                                               bn1_g, bn1_b, bn1_m, bn1_v,
                                               featA, 0, nullptr, nullptr, nullptr);

    // ---- criss-cross attention x2 (qkv via HMMA 1x1 conv) ----
    wprep_qkv_k<<<128, 256>>>(wq, wk, wv, wqkv);
    zero_border_k<<<1024, 256>>>(x2h, 128);
    float* F = featA;
    float* G = featB;
    for (int it = 0; it < 2; it++) {
        pad_k<<<dim3(64, CI/64, BB), 256>>>(F, CI, x2h, 128, 0);
        convmma_k<<<dim3(32, BB*2), 256, SM_TOTAL>>>(x2h, 128, CI/64, 1,
                                                     wqkv, CI, 256,
                                                     bq, bk, bv, nullptr,
                                                     qb, 3, kb, vb, vtb);
        trans_k<<<BB*CQ, 256>>>(kb, ktb);
        att_k<<<dim3(HH, BB), 256>>>(qb, kb, ktb, attb);
        oH_k<<<dim3(WW, BB), 256, OHW_SMEM>>>(attb, vtb, G);
        oW_k<<<dim3(HH, BB), 256, OHW_SMEM>>>(attb, vb, F, gamma, G);
        float* tmp = F; F = G; G = tmp;
    }
    // after 2 iters: F = featA, G = featB

    // ---- convb (128 -> 128) + BN2 ----
    wprep_k<<<576, 256>>>(convb_w, CI, CI, whi);
    pad_k<<<dim3(64, CI/64, BB), 256>>>(F, CI, x2h, 128, 0);
    convmma_k<<<dim3(32, BB), 256, SM_TOTAL>>>(x2h, 128, CI/64, 9,
                                               whi, CI, CI,
                                               bn2_g, bn2_b, bn2_m, bn2_v,
                                               G, 0, nullptr, nullptr, nullptr);

    // ---- bottleneck conv (concat 512+128 -> 512) + ELU ----
    pad_k<<<dim3(64, CI/64, BB), 256>>>(G, CI, xph, 640, CIN);
    wprep_k<<<4096, 256>>>(bott_w, CIN, CIN + CI, whi);
    convmma_k<<<dim3(32, BB*(CIN/128)), 256, SM_TOTAL>>>(xph, 640, (CIN + CI)/64, 9,
                                                         whi, CIN + CI, CIN,
                                                         nullptr, nullptr, nullptr, nullptr,
                                                         out, 1, nullptr, nullptr, nullptr);
}